// round 3
// baseline (speedup 1.0000x reference)
#include <cuda_runtime.h>

#define B_  4
#define S_  1024
#define E_  512
#define H_  8
#define D_  64
#define BH_ 32

// Scratch (no allocation allowed in kernel_launch -> __device__ globals).
static __device__ float g_CC [(size_t)BH_ * S_ * D_];   //   8 MB  [bh][t][d]
static __device__ float g_G  [(size_t)BH_ * S_ * S_];   // 128 MB  [bh][s][t] grammar scores, later W in-place
static __device__ float g_Sem[(size_t)BH_ * S_ * S_];   // 128 MB  [bh][s][t] semantic scores

__device__ __forceinline__ float fast_tanhf(float x) {
    // tanh(x) = 1 - 2/(exp(2x)+1); safe at +/-inf ends, ~1e-6 rel err.
    float e = __expf(2.0f * x);
    return 1.0f - __fdividef(2.0f, e + 1.0f);
}

// ---------------------------------------------------------------------------
// Kernel A: the sequential scan. One CTA per (b,h), one thread per d.
// CC[bh][t][d] = tanh(carry * pe);  carry <- k[t]*CC[t];  carry0 = k[0].
// ---------------------------------------------------------------------------
__global__ void scan_kernel(const float* __restrict__ tgt,
                            const float* __restrict__ enc) {
    const int bh = blockIdx.x, b = bh >> 3, h = bh & 7;
    const int d = threadIdx.x;
    const float pe = enc[h * D_ + d];
    const float* kp = tgt + (size_t)b * S_ * E_ + h * D_ + d;  // stride E_ per t
    float* cp = g_CC + (size_t)bh * S_ * D_ + d;               // stride D_ per t
    float carry = kp[0];
    for (int t = 0; t < S_; ++t) {
        float v = fast_tanhf(carry * pe);
        cp[(size_t)t * D_] = v;
        carry = kp[(size_t)t * E_] * v;
    }
}

// ---------------------------------------------------------------------------
// Kernel B: dual score GEMM. CTA = 64(s) x 64(t) tile of one head.
// Sem = (Q.K^T)/100, G = (Q.CC^T)/8. D=64 -> single reduction tile.
// Shared Q tile reused for both B-operands.
// ---------------------------------------------------------------------------
__global__ __launch_bounds__(256) void scores_kernel(const float* __restrict__ src,
                                                     const float* __restrict__ tgt) {
    __shared__ float Qs[D_ * 68];   // [d][s], padded row 68
    __shared__ float Ps[D_ * 68];   // [d][t], reused K then CC

    const int bh = blockIdx.z, b = bh >> 3, h = bh & 7;
    const int s0 = blockIdx.y << 6, t0 = blockIdx.x << 6;
    const int tid = threadIdx.x;

    for (int i = tid; i < 4096; i += 256) {
        int r = i >> 6, c = i & 63;
        Qs[c * 68 + r] = src[((size_t)b * S_ + s0 + r) * E_ + h * D_ + c];
        Ps[c * 68 + r] = tgt[((size_t)b * S_ + t0 + r) * E_ + h * D_ + c];
    }
    __syncthreads();

    const int tx = tid & 15, ty = tid >> 4;
    const int ss = ty << 2, tt = tx << 2;

    float accS[4][4] = {};
    #pragma unroll 8
    for (int d = 0; d < D_; ++d) {
        float4 a = *(const float4*)(Qs + d * 68 + ss);
        float4 p = *(const float4*)(Ps + d * 68 + tt);
        float av[4] = {a.x, a.y, a.z, a.w};
        float pv[4] = {p.x, p.y, p.z, p.w};
        #pragma unroll
        for (int i = 0; i < 4; ++i)
            #pragma unroll
            for (int j = 0; j < 4; ++j)
                accS[i][j] = fmaf(av[i], pv[j], accS[i][j]);
    }
    __syncthreads();

    for (int i = tid; i < 4096; i += 256) {
        int r = i >> 6, c = i & 63;
        Ps[c * 68 + r] = g_CC[((size_t)bh * S_ + t0 + r) * D_ + c];
    }
    __syncthreads();

    float accG[4][4] = {};
    #pragma unroll 8
    for (int d = 0; d < D_; ++d) {
        float4 a = *(const float4*)(Qs + d * 68 + ss);
        float4 p = *(const float4*)(Ps + d * 68 + tt);
        float av[4] = {a.x, a.y, a.z, a.w};
        float pv[4] = {p.x, p.y, p.z, p.w};
        #pragma unroll
        for (int i = 0; i < 4; ++i)
            #pragma unroll
            for (int j = 0; j < 4; ++j)
                accG[i][j] = fmaf(av[i], pv[j], accG[i][j]);
    }

    const size_t base = ((size_t)bh * S_ + s0 + ss) * S_ + t0 + tt;
    #pragma unroll
    for (int i = 0; i < 4; ++i) {
        float4 vs = make_float4(accS[i][0] * 0.01f,  accS[i][1] * 0.01f,
                                accS[i][2] * 0.01f,  accS[i][3] * 0.01f);
        float4 vg = make_float4(accG[i][0] * 0.125f, accG[i][1] * 0.125f,
                                accG[i][2] * 0.125f, accG[i][3] * 0.125f);
        *(float4*)(g_Sem + base + (size_t)i * S_) = vs;
        *(float4*)(g_G   + base + (size_t)i * S_) = vg;
    }
}

// ---------------------------------------------------------------------------
// Kernel C: per-row double softmax fusion, register-resident.
// gsm = softmax(G row); logits = (alpha*Sem + beta*gsm)/gamma; W = softmax(logits).
// W overwrites g_G in place (row-local). One warp processes 4 rows.
// ---------------------------------------------------------------------------
__global__ __launch_bounds__(256) void softmax_kernel(const float* __restrict__ pa,
                                                      const float* __restrict__ pb,
                                                      const float* __restrict__ pg) {
    const int bh = blockIdx.y;
    const int warp = threadIdx.x >> 5, lane = threadIdx.x & 31;
    const float alpha = *pa, beta = *pb, invg = 1.0f / *pg;

    for (int rr = 0; rr < 4; ++rr) {
        const int s = (blockIdx.x << 5) + (warp << 2) + rr;
        float* grow = g_G + ((size_t)bh * S_ + s) * S_;
        const float* srow = g_Sem + ((size_t)bh * S_ + s) * S_;

        float v[32];
        float m = -1e30f;
        #pragma unroll
        for (int i = 0; i < 32; ++i) { v[i] = grow[lane + (i << 5)]; m = fmaxf(m, v[i]); }
        #pragma unroll
        for (int o = 16; o; o >>= 1) m = fmaxf(m, __shfl_xor_sync(0xffffffffu, m, o));

        float sum = 0.f;
        #pragma unroll
        for (int i = 0; i < 32; ++i) { v[i] = __expf(v[i] - m); sum += v[i]; }
        #pragma unroll
        for (int o = 16; o; o >>= 1) sum += __shfl_xor_sync(0xffffffffu, sum, o);
        const float inv = __fdividef(1.0f, sum);

        float m2 = -1e30f;
        #pragma unroll
        for (int i = 0; i < 32; ++i) {
            float l = (alpha * srow[lane + (i << 5)] + beta * v[i] * inv) * invg;
            v[i] = l; m2 = fmaxf(m2, l);
        }
        #pragma unroll
        for (int o = 16; o; o >>= 1) m2 = fmaxf(m2, __shfl_xor_sync(0xffffffffu, m2, o));

        float s2 = 0.f;
        #pragma unroll
        for (int i = 0; i < 32; ++i) { v[i] = __expf(v[i] - m2); s2 += v[i]; }
        #pragma unroll
        for (int o = 16; o; o >>= 1) s2 += __shfl_xor_sync(0xffffffffu, s2, o);
        const float inv2 = __fdividef(1.0f, s2);

        #pragma unroll
        for (int i = 0; i < 32; ++i) grow[lane + (i << 5)] = v[i] * inv2;
    }
}

// ---------------------------------------------------------------------------
// Kernel D: output GEMM. O[bh][t][e] = sum_s W[bh][s][t] * target[b][s][e].
// CTA = 64(t) x 128(e), reduction s in chunks of 32. 4x8 microtile/thread.
// ---------------------------------------------------------------------------
__global__ __launch_bounds__(256) void out_gemm(const float* __restrict__ tgt,
                                                float* __restrict__ out) {
    __shared__ float As[32 * 64];    // [s][t]  (W rows: t contiguous)
    __shared__ float Bs[32 * 128];   // [s][e]

    const int bh = blockIdx.z, b = bh >> 3;
    const int t0 = blockIdx.x << 6, e0 = blockIdx.y << 7;
    const int tid = threadIdx.x;
    const int te = tid & 15, tg = tid >> 4;
    const int tt = tg << 2, ee = te << 3;

    const float* W = g_G + (size_t)bh * S_ * S_;
    const float* T = tgt + (size_t)b * S_ * E_;

    float acc[4][8] = {};
    for (int sc = 0; sc < S_; sc += 32) {
        for (int i = tid; i < 32 * 64; i += 256) {
            int r = i >> 6, c = i & 63;
            As[i] = W[(size_t)(sc + r) * S_ + t0 + c];
        }
        for (int i = tid; i < 32 * 128; i += 256) {
            int r = i >> 7, c = i & 127;
            Bs[i] = T[(size_t)(sc + r) * E_ + e0 + c];
        }
        __syncthreads();
        #pragma unroll 8
        for (int s = 0; s < 32; ++s) {
            float4 a  = *(const float4*)(As + s * 64 + tt);
            float4 b0 = *(const float4*)(Bs + s * 128 + ee);
            float4 b1 = *(const float4*)(Bs + s * 128 + ee + 4);
            float av[4] = {a.x, a.y, a.z, a.w};
            float bv[8] = {b0.x, b0.y, b0.z, b0.w, b1.x, b1.y, b1.z, b1.w};
            #pragma unroll
            for (int i = 0; i < 4; ++i)
                #pragma unroll
                for (int j = 0; j < 8; ++j)
                    acc[i][j] = fmaf(av[i], bv[j], acc[i][j]);
        }
        __syncthreads();
    }

    #pragma unroll
    for (int i = 0; i < 4; ++i) {
        float* o = out + ((size_t)bh * S_ + t0 + tt + i) * E_ + e0 + ee;
        *(float4*)(o)     = make_float4(acc[i][0], acc[i][1], acc[i][2], acc[i][3]);
        *(float4*)(o + 4) = make_float4(acc[i][4], acc[i][5], acc[i][6], acc[i][7]);
    }
}

// ---------------------------------------------------------------------------
extern "C" void kernel_launch(void* const* d_in, const int* in_sizes, int n_in,
                              void* d_out, int out_size) {
    (void)in_sizes; (void)n_in; (void)out_size;
    const float* src = (const float*)d_in[0];   // source (B,S,E)
    const float* tgt = (const float*)d_in[1];   // target (B,S,E)
    const float* enc = (const float*)d_in[2];   // encoder (1,H,1,D)
    const float* pa  = (const float*)d_in[3];   // alpha
    const float* pb  = (const float*)d_in[4];   // beta
    const float* pg  = (const float*)d_in[5];   // gamma
    float* out = (float*)d_out;                 // (B, H*S, E) fp32

    scan_kernel<<<BH_, D_>>>(tgt, enc);
    scores_kernel<<<dim3(16, 16, BH_), 256>>>(src, tgt);
    softmax_kernel<<<dim3(32, BH_), 256>>>(pa, pb, pg);
    out_gemm<<<dim3(16, 4, BH_), 256>>>(tgt, out);
}

// round 4
// speedup vs baseline: 1.5135x; 1.5135x over previous
#include <cuda_runtime.h>

#define B_  4
#define S_  1024
#define E_  512
#define H_  8
#define D_  64
#define BH_ 32

// Scratch (no allocation allowed in kernel_launch -> __device__ globals).
static __device__ float g_CC [(size_t)BH_ * S_ * D_];   //   8 MB  [bh][t][d]
static __device__ float g_G  [(size_t)BH_ * S_ * S_];   // 128 MB  [bh][s][t] grammar scores, later W in-place
static __device__ float g_Sem[(size_t)BH_ * S_ * S_];   // 128 MB  [bh][s][t] semantic scores

__device__ __forceinline__ float fast_tanhf(float x) {
    // tanh(x) = 1 - 2/(exp(2x)+1); safe at +/-inf ends, ~1e-6 rel err.
    float e = __expf(2.0f * x);
    return 1.0f - __fdividef(2.0f, e + 1.0f);
}

// ---------------------------------------------------------------------------
// Kernel A: the sequential scan. One CTA per (b,h), one thread per d.
// ---------------------------------------------------------------------------
__global__ void scan_kernel(const float* __restrict__ tgt,
                            const float* __restrict__ enc) {
    const int bh = blockIdx.x, b = bh >> 3, h = bh & 7;
    const int d = threadIdx.x;
    const float pe = enc[h * D_ + d];
    const float* kp = tgt + (size_t)b * S_ * E_ + h * D_ + d;  // stride E_ per t
    float* cp = g_CC + (size_t)bh * S_ * D_ + d;               // stride D_ per t
    float carry = kp[0];
    for (int t = 0; t < S_; ++t) {
        float v = fast_tanhf(carry * pe);
        cp[(size_t)t * D_] = v;
        carry = kp[(size_t)t * E_] * v;
    }
}

// ---------------------------------------------------------------------------
// Kernel B: dual score GEMM. CTA = 64(s) x 64(t) tile of one head.
// Sem = (Q.K^T)/100, G = (Q.CC^T)/8.
// ---------------------------------------------------------------------------
__global__ __launch_bounds__(256) void scores_kernel(const float* __restrict__ src,
                                                     const float* __restrict__ tgt) {
    __shared__ float Qs[D_ * 68];   // [d][s], padded row 68
    __shared__ float Ps[D_ * 68];   // [d][t], reused K then CC

    const int bh = blockIdx.z, b = bh >> 3, h = bh & 7;
    const int s0 = blockIdx.y << 6, t0 = blockIdx.x << 6;
    const int tid = threadIdx.x;

    for (int i = tid; i < 4096; i += 256) {
        int r = i >> 6, c = i & 63;
        Qs[c * 68 + r] = src[((size_t)b * S_ + s0 + r) * E_ + h * D_ + c];
        Ps[c * 68 + r] = tgt[((size_t)b * S_ + t0 + r) * E_ + h * D_ + c];
    }
    __syncthreads();

    const int tx = tid & 15, ty = tid >> 4;
    const int ss = ty << 2, tt = tx << 2;

    float accS[4][4] = {};
    #pragma unroll 8
    for (int d = 0; d < D_; ++d) {
        float4 a = *(const float4*)(Qs + d * 68 + ss);
        float4 p = *(const float4*)(Ps + d * 68 + tt);
        float av[4] = {a.x, a.y, a.z, a.w};
        float pv[4] = {p.x, p.y, p.z, p.w};
        #pragma unroll
        for (int i = 0; i < 4; ++i)
            #pragma unroll
            for (int j = 0; j < 4; ++j)
                accS[i][j] = fmaf(av[i], pv[j], accS[i][j]);
    }
    __syncthreads();

    for (int i = tid; i < 4096; i += 256) {
        int r = i >> 6, c = i & 63;
        Ps[c * 68 + r] = g_CC[((size_t)bh * S_ + t0 + r) * D_ + c];
    }
    __syncthreads();

    float accG[4][4] = {};
    #pragma unroll 8
    for (int d = 0; d < D_; ++d) {
        float4 a = *(const float4*)(Qs + d * 68 + ss);
        float4 p = *(const float4*)(Ps + d * 68 + tt);
        float av[4] = {a.x, a.y, a.z, a.w};
        float pv[4] = {p.x, p.y, p.z, p.w};
        #pragma unroll
        for (int i = 0; i < 4; ++i)
            #pragma unroll
            for (int j = 0; j < 4; ++j)
                accG[i][j] = fmaf(av[i], pv[j], accG[i][j]);
    }

    const size_t base = ((size_t)bh * S_ + s0 + ss) * S_ + t0 + tt;
    #pragma unroll
    for (int i = 0; i < 4; ++i) {
        float4 vs = make_float4(accS[i][0] * 0.01f,  accS[i][1] * 0.01f,
                                accS[i][2] * 0.01f,  accS[i][3] * 0.01f);
        float4 vg = make_float4(accG[i][0] * 0.125f, accG[i][1] * 0.125f,
                                accG[i][2] * 0.125f, accG[i][3] * 0.125f);
        *(float4*)(g_Sem + base + (size_t)i * S_) = vs;
        *(float4*)(g_G   + base + (size_t)i * S_) = vg;
    }
}

// ---------------------------------------------------------------------------
// Kernel C: per-row double softmax fusion, register-resident.
// ---------------------------------------------------------------------------
__global__ __launch_bounds__(256) void softmax_kernel(const float* __restrict__ pa,
                                                      const float* __restrict__ pb,
                                                      const float* __restrict__ pg) {
    const int bh = blockIdx.y;
    const int warp = threadIdx.x >> 5, lane = threadIdx.x & 31;
    const float alpha = *pa, beta = *pb, invg = 1.0f / *pg;

    for (int rr = 0; rr < 4; ++rr) {
        const int s = (blockIdx.x << 5) + (warp << 2) + rr;
        float* grow = g_G + ((size_t)bh * S_ + s) * S_;
        const float* srow = g_Sem + ((size_t)bh * S_ + s) * S_;

        float v[32];
        float m = -1e30f;
        #pragma unroll
        for (int i = 0; i < 32; ++i) { v[i] = grow[lane + (i << 5)]; m = fmaxf(m, v[i]); }
        #pragma unroll
        for (int o = 16; o; o >>= 1) m = fmaxf(m, __shfl_xor_sync(0xffffffffu, m, o));

        float sum = 0.f;
        #pragma unroll
        for (int i = 0; i < 32; ++i) { v[i] = __expf(v[i] - m); sum += v[i]; }
        #pragma unroll
        for (int o = 16; o; o >>= 1) sum += __shfl_xor_sync(0xffffffffu, sum, o);
        const float inv = __fdividef(1.0f, sum);

        float m2 = -1e30f;
        #pragma unroll
        for (int i = 0; i < 32; ++i) {
            float l = (alpha * srow[lane + (i << 5)] + beta * v[i] * inv) * invg;
            v[i] = l; m2 = fmaxf(m2, l);
        }
        #pragma unroll
        for (int o = 16; o; o >>= 1) m2 = fmaxf(m2, __shfl_xor_sync(0xffffffffu, m2, o));

        float s2 = 0.f;
        #pragma unroll
        for (int i = 0; i < 32; ++i) { v[i] = __expf(v[i] - m2); s2 += v[i]; }
        #pragma unroll
        for (int o = 16; o; o >>= 1) s2 += __shfl_xor_sync(0xffffffffu, s2, o);
        const float inv2 = __fdividef(1.0f, s2);

        #pragma unroll
        for (int i = 0; i < 32; ++i) grow[lane + (i << 5)] = v[i] * inv2;
    }
}

// ---------------------------------------------------------------------------
// Kernel D v2: output GEMM, FMA-bound tiling.
// O[bh][t][e] = sum_s W[bh][s][t] * target[b][s][e].
// CTA tile: 128(t) x 128(e). 256 threads, 8x8 microtile. k-chunk = 16 s-rows.
// Register-staged double-buffered shared memory.
// Per k-step/thread: 64B LDS -> 64 FMA; A-operand warp-broadcast => FMA-bound.
// ---------------------------------------------------------------------------
__global__ __launch_bounds__(256) void out_gemm(const float* __restrict__ tgt,
                                                float* __restrict__ out) {
    __shared__ float As[2][16][128];   // [buf][s][t]
    __shared__ float Bs[2][16][128];   // [buf][s][e]

    const int bh = blockIdx.z, b = bh >> 3;
    const int t0 = blockIdx.x << 7, e0 = blockIdx.y << 7;
    const int tid = threadIdx.x;

    const float* W = g_G + (size_t)bh * S_ * S_;
    const float* T = tgt + (size_t)b * S_ * E_;

    // Load mapping: 512 float4 per tile, 2 per thread (rows k and k+8).
    const int lk  = tid >> 5;          // 0..7
    const int lc  = (tid & 31) << 2;   // 0..124
    const float* gA = W + (size_t)lk * S_ + t0 + lc;   // advance 16*S_ per chunk
    const float* gB = T + (size_t)lk * E_ + e0 + lc;   // advance 16*E_ per chunk

    // Compute mapping: 8x8 microtile.
    const int tt = (tid >> 4) << 3;    // t offset 0..120
    const int ee = (tid & 15) << 3;    // e offset 0..120

    float acc[8][8] = {};
    float4 ra0, ra1, rb0, rb1;

    // Prologue: chunk 0 -> buf 0
    ra0 = *(const float4*)(gA);
    ra1 = *(const float4*)(gA + (size_t)8 * S_);
    rb0 = *(const float4*)(gB);
    rb1 = *(const float4*)(gB + (size_t)8 * E_);
    *(float4*)&As[0][lk][lc]     = ra0;
    *(float4*)&As[0][lk + 8][lc] = ra1;
    *(float4*)&Bs[0][lk][lc]     = rb0;
    *(float4*)&Bs[0][lk + 8][lc] = rb1;
    __syncthreads();

    const int NCHUNK = S_ / 16;   // 64
    for (int c = 0; c < NCHUNK; ++c) {
        const int cur = c & 1;
        if (c + 1 < NCHUNK) {
            const float* pA = gA + (size_t)(c + 1) * 16 * S_;
            const float* pB = gB + (size_t)(c + 1) * 16 * E_;
            ra0 = *(const float4*)(pA);
            ra1 = *(const float4*)(pA + (size_t)8 * S_);
            rb0 = *(const float4*)(pB);
            rb1 = *(const float4*)(pB + (size_t)8 * E_);
        }

        #pragma unroll
        for (int k = 0; k < 16; ++k) {
            float4 a0 = *(const float4*)&As[cur][k][tt];
            float4 a1 = *(const float4*)&As[cur][k][tt + 4];
            float4 b0 = *(const float4*)&Bs[cur][k][ee];
            float4 b1 = *(const float4*)&Bs[cur][k][ee + 4];
            float av[8] = {a0.x, a0.y, a0.z, a0.w, a1.x, a1.y, a1.z, a1.w};
            float bv[8] = {b0.x, b0.y, b0.z, b0.w, b1.x, b1.y, b1.z, b1.w};
            #pragma unroll
            for (int i = 0; i < 8; ++i)
                #pragma unroll
                for (int j = 0; j < 8; ++j)
                    acc[i][j] = fmaf(av[i], bv[j], acc[i][j]);
        }

        if (c + 1 < NCHUNK) {
            __syncthreads();
            const int nxt = cur ^ 1;
            *(float4*)&As[nxt][lk][lc]     = ra0;
            *(float4*)&As[nxt][lk + 8][lc] = ra1;
            *(float4*)&Bs[nxt][lk][lc]     = rb0;
            *(float4*)&Bs[nxt][lk + 8][lc] = rb1;
            __syncthreads();
        }
    }

    #pragma unroll
    for (int i = 0; i < 8; ++i) {
        float* o = out + ((size_t)bh * S_ + t0 + tt + i) * E_ + e0 + ee;
        *(float4*)(o)     = make_float4(acc[i][0], acc[i][1], acc[i][2], acc[i][3]);
        *(float4*)(o + 4) = make_float4(acc[i][4], acc[i][5], acc[i][6], acc[i][7]);
    }
}

// ---------------------------------------------------------------------------
extern "C" void kernel_launch(void* const* d_in, const int* in_sizes, int n_in,
                              void* d_out, int out_size) {
    (void)in_sizes; (void)n_in; (void)out_size;
    const float* src = (const float*)d_in[0];   // source (B,S,E)
    const float* tgt = (const float*)d_in[1];   // target (B,S,E)
    const float* enc = (const float*)d_in[2];   // encoder (1,H,1,D)
    const float* pa  = (const float*)d_in[3];   // alpha
    const float* pb  = (const float*)d_in[4];   // beta
    const float* pg  = (const float*)d_in[5];   // gamma
    float* out = (float*)d_out;                 // (B, H*S, E) fp32

    scan_kernel<<<BH_, D_>>>(tgt, enc);
    scores_kernel<<<dim3(16, 16, BH_), 256>>>(src, tgt);
    softmax_kernel<<<dim3(32, BH_), 256>>>(pa, pb, pg);
    out_gemm<<<dim3(8, 4, BH_), 256>>>(tgt, out);
}

// round 9
// speedup vs baseline: 2.0534x; 1.3567x over previous
#include <cuda_runtime.h>
#include <cuda_bf16.h>
#include <cstdint>

#define B_  4
#define S_  1024
#define E_  512
#define H_  8
#define D_  64
#define BH_ 32

// ---------------------------------------------------------------------------
// Scratch (__device__ globals; no runtime allocation allowed).
// ---------------------------------------------------------------------------
static __device__ float g_CC [(size_t)BH_ * S_ * D_];   //   8 MB [bh][t][d]
static __device__ float g_G  [(size_t)BH_ * S_ * S_];   // 128 MB [bh][s][t] -> W in place
static __device__ float g_Sem[(size_t)BH_ * S_ * S_];   // 128 MB [bh][s][t]
static __device__ __nv_bfloat16 g_Wt_hi[(size_t)BH_ * S_ * S_]; // 64 MB [bh][t][s]
static __device__ __nv_bfloat16 g_Wt_lo[(size_t)BH_ * S_ * S_]; // 64 MB
static __device__ __nv_bfloat16 g_Tt_hi[(size_t)B_ * E_ * S_];  //  4 MB [b][e][s]
static __device__ __nv_bfloat16 g_Tt_lo[(size_t)B_ * E_ * S_];  //  4 MB

__device__ __forceinline__ float fast_tanhf(float x) {
    float e = __expf(2.0f * x);
    return 1.0f - __fdividef(2.0f, e + 1.0f);
}

__device__ __forceinline__ uint32_t smem_u32(const void* p) {
    uint32_t a;
    asm("{ .reg .u64 t; cvta.to.shared.u64 t, %1; cvt.u32.u64 %0, t; }" : "=r"(a) : "l"(p));
    return a;
}
__device__ __forceinline__ void ldsm_x4(uint32_t* r, uint32_t a) {
    asm volatile("ldmatrix.sync.aligned.m8n8.x4.shared.b16 {%0,%1,%2,%3}, [%4];"
        : "=r"(r[0]), "=r"(r[1]), "=r"(r[2]), "=r"(r[3]) : "r"(a));
}
__device__ __forceinline__ void ldsm_x2(uint32_t* r, uint32_t a) {
    asm volatile("ldmatrix.sync.aligned.m8n8.x2.shared.b16 {%0,%1}, [%2];"
        : "=r"(r[0]), "=r"(r[1]) : "r"(a));
}
__device__ __forceinline__ void mma16816(float* c, const uint32_t* a, const uint32_t* b) {
    asm volatile("mma.sync.aligned.m16n8k16.row.col.f32.bf16.bf16.f32 "
        "{%0,%1,%2,%3}, {%4,%5,%6,%7}, {%8,%9}, {%0,%1,%2,%3};"
        : "+f"(c[0]), "+f"(c[1]), "+f"(c[2]), "+f"(c[3])
        : "r"(a[0]), "r"(a[1]), "r"(a[2]), "r"(a[3]), "r"(b[0]), "r"(b[1]));
}

// ---------------------------------------------------------------------------
// Kernel A: sequential scan.
// ---------------------------------------------------------------------------
__global__ void scan_kernel(const float* __restrict__ tgt,
                            const float* __restrict__ enc) {
    const int bh = blockIdx.x, b = bh >> 3, h = bh & 7;
    const int d = threadIdx.x;
    const float pe = enc[h * D_ + d];
    const float* kp = tgt + (size_t)b * S_ * E_ + h * D_ + d;
    float* cp = g_CC + (size_t)bh * S_ * D_ + d;
    float carry = kp[0];
    for (int t = 0; t < S_; ++t) {
        float v = fast_tanhf(carry * pe);
        cp[(size_t)t * D_] = v;
        carry = kp[(size_t)t * E_] * v;
    }
}

// ---------------------------------------------------------------------------
// Kernel B: dual score GEMM (64x64 tile, fp32 FFMA).
// ---------------------------------------------------------------------------
__global__ __launch_bounds__(256) void scores_kernel(const float* __restrict__ src,
                                                     const float* __restrict__ tgt) {
    __shared__ float Qs[D_ * 68];
    __shared__ float Ps[D_ * 68];

    const int bh = blockIdx.z, b = bh >> 3, h = bh & 7;
    const int s0 = blockIdx.y << 6, t0 = blockIdx.x << 6;
    const int tid = threadIdx.x;

    for (int i = tid; i < 4096; i += 256) {
        int r = i >> 6, c = i & 63;
        Qs[c * 68 + r] = src[((size_t)b * S_ + s0 + r) * E_ + h * D_ + c];
        Ps[c * 68 + r] = tgt[((size_t)b * S_ + t0 + r) * E_ + h * D_ + c];
    }
    __syncthreads();

    const int tx = tid & 15, ty = tid >> 4;
    const int ss = ty << 2, tt = tx << 2;

    float accS[4][4] = {};
    #pragma unroll 8
    for (int d = 0; d < D_; ++d) {
        float4 a = *(const float4*)(Qs + d * 68 + ss);
        float4 p = *(const float4*)(Ps + d * 68 + tt);
        float av[4] = {a.x, a.y, a.z, a.w};
        float pv[4] = {p.x, p.y, p.z, p.w};
        #pragma unroll
        for (int i = 0; i < 4; ++i)
            #pragma unroll
            for (int j = 0; j < 4; ++j)
                accS[i][j] = fmaf(av[i], pv[j], accS[i][j]);
    }
    __syncthreads();

    for (int i = tid; i < 4096; i += 256) {
        int r = i >> 6, c = i & 63;
        Ps[c * 68 + r] = g_CC[((size_t)bh * S_ + t0 + r) * D_ + c];
    }
    __syncthreads();

    float accG[4][4] = {};
    #pragma unroll 8
    for (int d = 0; d < D_; ++d) {
        float4 a = *(const float4*)(Qs + d * 68 + ss);
        float4 p = *(const float4*)(Ps + d * 68 + tt);
        float av[4] = {a.x, a.y, a.z, a.w};
        float pv[4] = {p.x, p.y, p.z, p.w};
        #pragma unroll
        for (int i = 0; i < 4; ++i)
            #pragma unroll
            for (int j = 0; j < 4; ++j)
                accG[i][j] = fmaf(av[i], pv[j], accG[i][j]);
    }

    const size_t base = ((size_t)bh * S_ + s0 + ss) * S_ + t0 + tt;
    #pragma unroll
    for (int i = 0; i < 4; ++i) {
        float4 vs = make_float4(accS[i][0] * 0.01f,  accS[i][1] * 0.01f,
                                accS[i][2] * 0.01f,  accS[i][3] * 0.01f);
        float4 vg = make_float4(accG[i][0] * 0.125f, accG[i][1] * 0.125f,
                                accG[i][2] * 0.125f, accG[i][3] * 0.125f);
        *(float4*)(g_Sem + base + (size_t)i * S_) = vs;
        *(float4*)(g_G   + base + (size_t)i * S_) = vg;
    }
}

// ---------------------------------------------------------------------------
// Kernel C: per-row double softmax, register-resident. W overwrites g_G.
// ---------------------------------------------------------------------------
__global__ __launch_bounds__(256) void softmax_kernel(const float* __restrict__ pa,
                                                      const float* __restrict__ pb,
                                                      const float* __restrict__ pg) {
    const int bh = blockIdx.y;
    const int warp = threadIdx.x >> 5, lane = threadIdx.x & 31;
    const float alpha = *pa, beta = *pb, invg = 1.0f / *pg;

    for (int rr = 0; rr < 4; ++rr) {
        const int s = (blockIdx.x << 5) + (warp << 2) + rr;
        float* grow = g_G + ((size_t)bh * S_ + s) * S_;
        const float* srow = g_Sem + ((size_t)bh * S_ + s) * S_;

        float v[32];
        float m = -1e30f;
        #pragma unroll
        for (int i = 0; i < 32; ++i) { v[i] = grow[lane + (i << 5)]; m = fmaxf(m, v[i]); }
        #pragma unroll
        for (int o = 16; o; o >>= 1) m = fmaxf(m, __shfl_xor_sync(0xffffffffu, m, o));

        float sum = 0.f;
        #pragma unroll
        for (int i = 0; i < 32; ++i) { v[i] = __expf(v[i] - m); sum += v[i]; }
        #pragma unroll
        for (int o = 16; o; o >>= 1) sum += __shfl_xor_sync(0xffffffffu, sum, o);
        const float inv = __fdividef(1.0f, sum);

        float m2 = -1e30f;
        #pragma unroll
        for (int i = 0; i < 32; ++i) {
            float l = (alpha * srow[lane + (i << 5)] + beta * v[i] * inv) * invg;
            v[i] = l; m2 = fmaxf(m2, l);
        }
        #pragma unroll
        for (int o = 16; o; o >>= 1) m2 = fmaxf(m2, __shfl_xor_sync(0xffffffffu, m2, o));

        float s2 = 0.f;
        #pragma unroll
        for (int i = 0; i < 32; ++i) { v[i] = __expf(v[i] - m2); s2 += v[i]; }
        #pragma unroll
        for (int o = 16; o; o >>= 1) s2 += __shfl_xor_sync(0xffffffffu, s2, o);
        const float inv2 = __fdividef(1.0f, s2);

        #pragma unroll
        for (int i = 0; i < 32; ++i) grow[lane + (i << 5)] = v[i] * inv2;
    }
}

// ---------------------------------------------------------------------------
// Split + transpose: in [z][R][C] fp32 -> out hi/lo [z][C][R] bf16.
// Grid MUST be (C/32, R/32, Z): blockIdx.x -> columns, blockIdx.y -> rows.
// ---------------------------------------------------------------------------
__device__ __forceinline__ void split_transpose_body(const float* __restrict__ in,
                                                     __nv_bfloat16* __restrict__ oh,
                                                     __nv_bfloat16* __restrict__ ol,
                                                     int R, int C) {
    __shared__ float tl[32][33];
    const int c0 = blockIdx.x << 5, r0 = blockIdx.y << 5;
    const size_t zo = (size_t)blockIdx.z * R * C;
    const int tx = threadIdx.x, ty = threadIdx.y;

    #pragma unroll
    for (int i = 0; i < 4; ++i)
        tl[ty + i * 8][tx] = in[zo + (size_t)(r0 + ty + i * 8) * C + c0 + tx];
    __syncthreads();

    #pragma unroll
    for (int i = 0; i < 4; ++i) {
        float v = tl[tx][ty + i * 8];
        __nv_bfloat16 h = __float2bfloat16(v);
        __nv_bfloat16 l = __float2bfloat16(v - __bfloat162float(h));
        size_t idx = zo + (size_t)(c0 + ty + i * 8) * R + r0 + tx;
        oh[idx] = h;
        ol[idx] = l;
    }
}

__global__ void prep_W() {   // g_G (W) [bh][s][t] -> Wt [bh][t][s]
    split_transpose_body(g_G, g_Wt_hi, g_Wt_lo, S_, S_);
}
__global__ void prep_T(const float* __restrict__ tgt) {  // [b][s][e] -> Tt [b][e][s]
    split_transpose_body(tgt, g_Tt_hi, g_Tt_lo, S_, E_);
}

// ---------------------------------------------------------------------------
// Kernel D v4: split-bf16 warp-MMA output GEMM (mma.sync.m16n8k16, HMMA).
// O[bh][t][e] = sum_s W[s,t]*T[s,e]  =  A[t,s] (row) x B[e,s] (col), K = s.
// CTA 128x128, 8 warps, warp tile 64x32 (4 m-tiles x 4 n-tiles).
// k-chunk 32, double-buffered smem, rows padded to 40 bf16 (80 B).
// Split: D = Ah*Bh + Al*Bh + Ah*Bl.
// Each thread loads TWO 16B quads per tile array (full 128x32 coverage).
// ---------------------------------------------------------------------------
#define KC_       32
#define NCHUNK_   (S_ / KC_)             // 32
#define RSTRIDE_  40                     // bf16 elems per row (80 bytes)
#define TILEB_    (128 * RSTRIDE_ * 2)   // 10240 B per 128x32 tile
#define OFF_AH_   0
#define OFF_AL_   TILEB_
#define OFF_BH_   (2 * TILEB_)
#define OFF_BL_   (3 * TILEB_)
#define BUFB_     (4 * TILEB_)           // 40960 B
#define SMEM_MMA  (2 * BUFB_)            // 81920 B

__global__ __launch_bounds__(256) void out_gemm_mma(float* __restrict__ out) {
    extern __shared__ char smem[];
    const uint32_t sb = smem_u32(smem);

    const int tid = threadIdx.x, wid = tid >> 5, lane = tid & 31;
    const int bh = blockIdx.z, b = bh >> 3;
    const int t0 = blockIdx.x << 7, e0 = blockIdx.y << 7;

    const __nv_bfloat16* WH = g_Wt_hi + ((size_t)bh * S_ + t0) * S_;
    const __nv_bfloat16* WL = g_Wt_lo + ((size_t)bh * S_ + t0) * S_;
    const __nv_bfloat16* TH = g_Tt_hi + ((size_t)b * E_ + e0) * S_;
    const __nv_bfloat16* TL = g_Tt_lo + ((size_t)b * E_ + e0) * S_;

    // Global->smem mapping: TWO 16B quads per thread per tile array.
    // row = tid>>1 (0..127), column halves (tid&1)*16 + {0, 8} (bf16 units).
    const int lrow = tid >> 1;
    const int lcb  = (tid & 1) << 4;            // 0 or 16
    const uint32_t so0 = (uint32_t)(lrow * (RSTRIDE_ * 2) + lcb * 2);
    const uint32_t so1 = so0 + 16;              // +8 bf16

    // Warp tile origin.
    const int wm = (wid >> 2) * 64;             // 0 / 64   (t)
    const int wn = (wid & 3) * 32;              // 0..96    (e)

    float acc[4][4][4] = {};

    // ---- prologue: chunk 0 -> buffer 0 ----
    {
        const size_t g0 = (size_t)lrow * S_ + lcb;
        const size_t g1 = g0 + 8;
        *(uint4*)(smem + OFF_AH_ + so0) = *(const uint4*)(WH + g0);
        *(uint4*)(smem + OFF_AH_ + so1) = *(const uint4*)(WH + g1);
        *(uint4*)(smem + OFF_AL_ + so0) = *(const uint4*)(WL + g0);
        *(uint4*)(smem + OFF_AL_ + so1) = *(const uint4*)(WL + g1);
        *(uint4*)(smem + OFF_BH_ + so0) = *(const uint4*)(TH + g0);
        *(uint4*)(smem + OFF_BH_ + so1) = *(const uint4*)(TH + g1);
        *(uint4*)(smem + OFF_BL_ + so0) = *(const uint4*)(TL + g0);
        *(uint4*)(smem + OFF_BL_ + so1) = *(const uint4*)(TL + g1);
        __syncthreads();
    }

    // ldmatrix per-lane address components.
    const int a_r = lane & 15, a_c = (lane >> 4) << 3;          // A x4
    const int b_r = lane & 7,  b_c = ((lane >> 3) & 1) << 3;    // B x2

    for (int c = 0; c < NCHUNK_; ++c) {
        const int cur = c & 1, nxt = cur ^ 1;
        const bool have_next = (c + 1 < NCHUNK_);

        uint4 vah, vah1, val, val1, vbh, vbh1, vbl, vbl1;
        if (have_next) {
            const size_t g0 = (size_t)lrow * S_ + (size_t)(c + 1) * KC_ + lcb;
            const size_t g1 = g0 + 8;
            vah  = *(const uint4*)(WH + g0);  vah1 = *(const uint4*)(WH + g1);
            val  = *(const uint4*)(WL + g0);  val1 = *(const uint4*)(WL + g1);
            vbh  = *(const uint4*)(TH + g0);  vbh1 = *(const uint4*)(TH + g1);
            vbl  = *(const uint4*)(TL + g0);  vbl1 = *(const uint4*)(TL + g1);
        }

        const uint32_t base = sb + (uint32_t)cur * BUFB_;
        #pragma unroll
        for (int kk = 0; kk < 2; ++kk) {
            const int k0 = kk << 4;
            uint32_t Ah[4][4], Al[4][4], Bh[4][2], Bl[4][2];
            #pragma unroll
            for (int mi = 0; mi < 4; ++mi)
                ldsm_x4(Ah[mi], base + OFF_AH_ +
                        (uint32_t)((wm + mi * 16 + a_r) * (RSTRIDE_ * 2) + (a_c + k0) * 2));
            #pragma unroll
            for (int ni = 0; ni < 4; ++ni) {
                const uint32_t ro = (uint32_t)((wn + ni * 8 + b_r) * (RSTRIDE_ * 2) + (b_c + k0) * 2);
                ldsm_x2(Bh[ni], base + OFF_BH_ + ro);
                ldsm_x2(Bl[ni], base + OFF_BL_ + ro);
            }
            #pragma unroll
            for (int mi = 0; mi < 4; ++mi)
                #pragma unroll
                for (int ni = 0; ni < 4; ++ni)
                    mma16816(acc[mi][ni], Ah[mi], Bh[ni]);
            #pragma unroll
            for (int mi = 0; mi < 4; ++mi)
                #pragma unroll
                for (int ni = 0; ni < 4; ++ni)
                    mma16816(acc[mi][ni], Ah[mi], Bl[ni]);
            #pragma unroll
            for (int mi = 0; mi < 4; ++mi)
                ldsm_x4(Al[mi], base + OFF_AL_ +
                        (uint32_t)((wm + mi * 16 + a_r) * (RSTRIDE_ * 2) + (a_c + k0) * 2));
            #pragma unroll
            for (int mi = 0; mi < 4; ++mi)
                #pragma unroll
                for (int ni = 0; ni < 4; ++ni)
                    mma16816(acc[mi][ni], Al[mi], Bh[ni]);
        }

        __syncthreads();
        if (have_next) {
            char* dst = smem + nxt * BUFB_;
            *(uint4*)(dst + OFF_AH_ + so0) = vah;
            *(uint4*)(dst + OFF_AH_ + so1) = vah1;
            *(uint4*)(dst + OFF_AL_ + so0) = val;
            *(uint4*)(dst + OFF_AL_ + so1) = val1;
            *(uint4*)(dst + OFF_BH_ + so0) = vbh;
            *(uint4*)(dst + OFF_BH_ + so1) = vbh1;
            *(uint4*)(dst + OFF_BL_ + so0) = vbl;
            *(uint4*)(dst + OFF_BL_ + so1) = vbl1;
        }
        __syncthreads();
    }

    // ---- epilogue ----
    #pragma unroll
    for (int mi = 0; mi < 4; ++mi) {
        const int t = t0 + wm + mi * 16 + (lane >> 2);
        #pragma unroll
        for (int ni = 0; ni < 4; ++ni) {
            const int e = e0 + wn + ni * 8 + ((lane & 3) << 1);
            float* o = out + ((size_t)bh * S_ + t) * E_ + e;
            *(float2*)o            = make_float2(acc[mi][ni][0], acc[mi][ni][1]);
            *(float2*)(o + 8 * E_) = make_float2(acc[mi][ni][2], acc[mi][ni][3]);
        }
    }
}

// ---------------------------------------------------------------------------
extern "C" void kernel_launch(void* const* d_in, const int* in_sizes, int n_in,
                              void* d_out, int out_size) {
    (void)in_sizes; (void)n_in; (void)out_size;
    const float* src = (const float*)d_in[0];
    const float* tgt = (const float*)d_in[1];
    const float* enc = (const float*)d_in[2];
    const float* pa  = (const float*)d_in[3];
    const float* pb  = (const float*)d_in[4];
    const float* pg  = (const float*)d_in[5];
    float* out = (float*)d_out;

    cudaFuncSetAttribute(out_gemm_mma, cudaFuncAttributeMaxDynamicSharedMemorySize, SMEM_MMA);

    scan_kernel<<<BH_, D_>>>(tgt, enc);
    prep_T<<<dim3(E_ / 32, S_ / 32, B_), dim3(32, 8)>>>(tgt);   // (cols, rows, z) !
    scores_kernel<<<dim3(16, 16, BH_), 256>>>(src, tgt);
    softmax_kernel<<<dim3(32, BH_), 256>>>(pa, pb, pg);
    prep_W<<<dim3(S_ / 32, S_ / 32, BH_), dim3(32, 8)>>>();
    out_gemm_mma<<<dim3(8, 4, BH_), 256, SMEM_MMA>>>(out);
}

// round 10
// speedup vs baseline: 2.4142x; 1.1757x over previous
#include <cuda_runtime.h>
#include <cuda_bf16.h>
#include <cstdint>

#define B_  4
#define S_  1024
#define E_  512
#define H_  8
#define D_  64
#define BH_ 32

// ---------------------------------------------------------------------------
// Scratch (__device__ globals; no runtime allocation allowed).
// ---------------------------------------------------------------------------
static __device__ float g_CC [(size_t)BH_ * S_ * D_];   //   8 MB [bh][t][d]
static __device__ float g_G  [(size_t)BH_ * S_ * S_];   // 128 MB [bh][s][t] -> W in place
static __device__ float g_Sem[(size_t)BH_ * S_ * S_];   // 128 MB [bh][s][t]
static __device__ __nv_bfloat16 g_Wt_hi[(size_t)BH_ * S_ * S_]; // 64 MB [bh][t][s]
static __device__ __nv_bfloat16 g_Wt_lo[(size_t)BH_ * S_ * S_]; // 64 MB
static __device__ __nv_bfloat16 g_Tt_hi[(size_t)B_ * E_ * S_];  //  4 MB [b][e][s]
static __device__ __nv_bfloat16 g_Tt_lo[(size_t)B_ * E_ * S_];  //  4 MB

__device__ __forceinline__ float fast_tanhf(float x) {
    float e = __expf(2.0f * x);
    return 1.0f - __fdividef(2.0f, e + 1.0f);
}

__device__ __forceinline__ uint32_t smem_u32(const void* p) {
    uint32_t a;
    asm("{ .reg .u64 t; cvta.to.shared.u64 t, %1; cvt.u32.u64 %0, t; }" : "=r"(a) : "l"(p));
    return a;
}
__device__ __forceinline__ void ldsm_x4(uint32_t* r, uint32_t a) {
    asm volatile("ldmatrix.sync.aligned.m8n8.x4.shared.b16 {%0,%1,%2,%3}, [%4];"
        : "=r"(r[0]), "=r"(r[1]), "=r"(r[2]), "=r"(r[3]) : "r"(a));
}
__device__ __forceinline__ void ldsm_x2(uint32_t* r, uint32_t a) {
    asm volatile("ldmatrix.sync.aligned.m8n8.x2.shared.b16 {%0,%1}, [%2];"
        : "=r"(r[0]), "=r"(r[1]) : "r"(a));
}
__device__ __forceinline__ void mma16816(float* c, const uint32_t* a, const uint32_t* b) {
    asm volatile("mma.sync.aligned.m16n8k16.row.col.f32.bf16.bf16.f32 "
        "{%0,%1,%2,%3}, {%4,%5,%6,%7}, {%8,%9}, {%0,%1,%2,%3};"
        : "+f"(c[0]), "+f"(c[1]), "+f"(c[2]), "+f"(c[3])
        : "r"(a[0]), "r"(a[1]), "r"(a[2]), "r"(a[3]), "r"(b[0]), "r"(b[1]));
}

// ---------------------------------------------------------------------------
// Kernel A: sequential scan.
// ---------------------------------------------------------------------------
__global__ void scan_kernel(const float* __restrict__ tgt,
                            const float* __restrict__ enc) {
    const int bh = blockIdx.x, b = bh >> 3, h = bh & 7;
    const int d = threadIdx.x;
    const float pe = enc[h * D_ + d];
    const float* kp = tgt + (size_t)b * S_ * E_ + h * D_ + d;
    float* cp = g_CC + (size_t)bh * S_ * D_ + d;
    float carry = kp[0];
    for (int t = 0; t < S_; ++t) {
        float v = fast_tanhf(carry * pe);
        cp[(size_t)t * D_] = v;
        carry = kp[(size_t)t * E_] * v;
    }
}

// ---------------------------------------------------------------------------
// Kernel B v2: dual score GEMM on tensor cores (split-bf16 HMMA).
// Sem = (Q.K^T)/100, G = (Q.CC^T)/8. A=Q[s][d] row, B=[t][d] col, K=d=64.
// CTA 128(s)x128(t), 8 warps (64x32), rows padded to 72 bf16 (144 B).
// fp32 -> hi/lo bf16 conversion fused into smem staging.
// Two passes reuse the Q tiles; P-buffer holds K then CC.
// ---------------------------------------------------------------------------
#define SC_RST    72
#define SC_TILEB  (128 * SC_RST * 2)   // 18432 B
#define SC_QH     0
#define SC_QL     SC_TILEB
#define SC_PH     (2 * SC_TILEB)
#define SC_PL     (3 * SC_TILEB)
#define SMEM_SC   (4 * SC_TILEB)       // 73728 B

__device__ __forceinline__ void load_split_64(const float* __restrict__ g, int gstride,
                                              char* sh, char* sl, int tid) {
    #pragma unroll
    for (int i = 0; i < 8; ++i) {
        const int q = i * 256 + tid;        // 0..2047 quads
        const int row = q >> 4;             // 16 quads per 64-col row
        const int col = (q & 15) << 2;
        const float4 v = *(const float4*)(g + (size_t)row * gstride + col);
        const __nv_bfloat16 h0 = __float2bfloat16(v.x);
        const __nv_bfloat16 h1 = __float2bfloat16(v.y);
        const __nv_bfloat16 h2 = __float2bfloat16(v.z);
        const __nv_bfloat16 h3 = __float2bfloat16(v.w);
        const __nv_bfloat16 l0 = __float2bfloat16(v.x - __bfloat162float(h0));
        const __nv_bfloat16 l1 = __float2bfloat16(v.y - __bfloat162float(h1));
        const __nv_bfloat16 l2 = __float2bfloat16(v.z - __bfloat162float(h2));
        const __nv_bfloat16 l3 = __float2bfloat16(v.w - __bfloat162float(h3));
        const uint32_t hp0 = ((uint32_t)__bfloat16_as_ushort(h1) << 16) | __bfloat16_as_ushort(h0);
        const uint32_t hp1 = ((uint32_t)__bfloat16_as_ushort(h3) << 16) | __bfloat16_as_ushort(h2);
        const uint32_t lp0 = ((uint32_t)__bfloat16_as_ushort(l1) << 16) | __bfloat16_as_ushort(l0);
        const uint32_t lp1 = ((uint32_t)__bfloat16_as_ushort(l3) << 16) | __bfloat16_as_ushort(l2);
        const uint32_t off = (uint32_t)(row * (SC_RST * 2) + col * 2);
        *(uint2*)(sh + off) = make_uint2(hp0, hp1);
        *(uint2*)(sl + off) = make_uint2(lp0, lp1);
    }
}

__global__ __launch_bounds__(256) void scores_mma(const float* __restrict__ src,
                                                  const float* __restrict__ tgt) {
    extern __shared__ char smem[];
    const uint32_t sb = smem_u32(smem);

    const int tid = threadIdx.x, wid = tid >> 5, lane = tid & 31;
    const int bh = blockIdx.z, b = bh >> 3, h = bh & 7;
    const int s0 = blockIdx.y << 7, t0 = blockIdx.x << 7;

    // Stage Q and K tiles (fp32 -> hi/lo bf16).
    load_split_64(src + ((size_t)(b * S_ + s0)) * E_ + h * D_, E_,
                  smem + SC_QH, smem + SC_QL, tid);
    load_split_64(tgt + ((size_t)(b * S_ + t0)) * E_ + h * D_, E_,
                  smem + SC_PH, smem + SC_PL, tid);
    __syncthreads();

    const int wm = (wid >> 2) * 64;    // s offset 0/64
    const int wn = (wid & 3) * 32;     // t offset 0..96
    const int a_r = lane & 15, a_c = (lane >> 4) << 3;
    const int b_r = lane & 7,  b_c = ((lane >> 3) & 1) << 3;

    float acc[4][4][4] = {};

    // ---- pass 1: Sem = Q x K ----
    #pragma unroll
    for (int k = 0; k < 4; ++k) {
        const int k0 = k << 4;
        uint32_t Ah[4][4], Al[4][4], Bh[4][2], Bl[4][2];
        #pragma unroll
        for (int mi = 0; mi < 4; ++mi) {
            const uint32_t ro = (uint32_t)((wm + mi * 16 + a_r) * (SC_RST * 2) + (a_c + k0) * 2);
            ldsm_x4(Ah[mi], sb + SC_QH + ro);
            ldsm_x4(Al[mi], sb + SC_QL + ro);
        }
        #pragma unroll
        for (int ni = 0; ni < 4; ++ni) {
            const uint32_t ro = (uint32_t)((wn + ni * 8 + b_r) * (SC_RST * 2) + (b_c + k0) * 2);
            ldsm_x2(Bh[ni], sb + SC_PH + ro);
            ldsm_x2(Bl[ni], sb + SC_PL + ro);
        }
        #pragma unroll
        for (int mi = 0; mi < 4; ++mi)
            #pragma unroll
            for (int ni = 0; ni < 4; ++ni) {
                mma16816(acc[mi][ni], Ah[mi], Bh[ni]);
                mma16816(acc[mi][ni], Al[mi], Bh[ni]);
                mma16816(acc[mi][ni], Ah[mi], Bl[ni]);
            }
    }

    #pragma unroll
    for (int mi = 0; mi < 4; ++mi) {
        const int s = s0 + wm + mi * 16 + (lane >> 2);
        #pragma unroll
        for (int ni = 0; ni < 4; ++ni) {
            const int t = t0 + wn + ni * 8 + ((lane & 3) << 1);
            float* o = g_Sem + ((size_t)bh * S_ + s) * S_ + t;
            *(float2*)o            = make_float2(acc[mi][ni][0] * 0.01f, acc[mi][ni][1] * 0.01f);
            *(float2*)(o + 8 * S_) = make_float2(acc[mi][ni][2] * 0.01f, acc[mi][ni][3] * 0.01f);
        }
    }
    __syncthreads();   // all warps done reading P before overwrite

    // Stage CC into the P buffer (contiguous rows, stride D_).
    load_split_64(g_CC + ((size_t)(bh * S_ + t0)) * D_, D_,
                  smem + SC_PH, smem + SC_PL, tid);
    __syncthreads();

    // ---- pass 2: G = Q x CC ----
    #pragma unroll
    for (int mi = 0; mi < 4; ++mi)
        #pragma unroll
        for (int ni = 0; ni < 4; ++ni)
            #pragma unroll
            for (int x = 0; x < 4; ++x)
                acc[mi][ni][x] = 0.f;

    #pragma unroll
    for (int k = 0; k < 4; ++k) {
        const int k0 = k << 4;
        uint32_t Ah[4][4], Al[4][4], Bh[4][2], Bl[4][2];
        #pragma unroll
        for (int mi = 0; mi < 4; ++mi) {
            const uint32_t ro = (uint32_t)((wm + mi * 16 + a_r) * (SC_RST * 2) + (a_c + k0) * 2);
            ldsm_x4(Ah[mi], sb + SC_QH + ro);
            ldsm_x4(Al[mi], sb + SC_QL + ro);
        }
        #pragma unroll
        for (int ni = 0; ni < 4; ++ni) {
            const uint32_t ro = (uint32_t)((wn + ni * 8 + b_r) * (SC_RST * 2) + (b_c + k0) * 2);
            ldsm_x2(Bh[ni], sb + SC_PH + ro);
            ldsm_x2(Bl[ni], sb + SC_PL + ro);
        }
        #pragma unroll
        for (int mi = 0; mi < 4; ++mi)
            #pragma unroll
            for (int ni = 0; ni < 4; ++ni) {
                mma16816(acc[mi][ni], Ah[mi], Bh[ni]);
                mma16816(acc[mi][ni], Al[mi], Bh[ni]);
                mma16816(acc[mi][ni], Ah[mi], Bl[ni]);
            }
    }

    #pragma unroll
    for (int mi = 0; mi < 4; ++mi) {
        const int s = s0 + wm + mi * 16 + (lane >> 2);
        #pragma unroll
        for (int ni = 0; ni < 4; ++ni) {
            const int t = t0 + wn + ni * 8 + ((lane & 3) << 1);
            float* o = g_G + ((size_t)bh * S_ + s) * S_ + t;
            *(float2*)o            = make_float2(acc[mi][ni][0] * 0.125f, acc[mi][ni][1] * 0.125f);
            *(float2*)(o + 8 * S_) = make_float2(acc[mi][ni][2] * 0.125f, acc[mi][ni][3] * 0.125f);
        }
    }
}

// ---------------------------------------------------------------------------
// Kernel C: per-row double softmax, register-resident. W overwrites g_G.
// ---------------------------------------------------------------------------
__global__ __launch_bounds__(256) void softmax_kernel(const float* __restrict__ pa,
                                                      const float* __restrict__ pb,
                                                      const float* __restrict__ pg) {
    const int bh = blockIdx.y;
    const int warp = threadIdx.x >> 5, lane = threadIdx.x & 31;
    const float alpha = *pa, beta = *pb, invg = 1.0f / *pg;

    for (int rr = 0; rr < 4; ++rr) {
        const int s = (blockIdx.x << 5) + (warp << 2) + rr;
        float* grow = g_G + ((size_t)bh * S_ + s) * S_;
        const float* srow = g_Sem + ((size_t)bh * S_ + s) * S_;

        float v[32];
        float m = -1e30f;
        #pragma unroll
        for (int i = 0; i < 32; ++i) { v[i] = grow[lane + (i << 5)]; m = fmaxf(m, v[i]); }
        #pragma unroll
        for (int o = 16; o; o >>= 1) m = fmaxf(m, __shfl_xor_sync(0xffffffffu, m, o));

        float sum = 0.f;
        #pragma unroll
        for (int i = 0; i < 32; ++i) { v[i] = __expf(v[i] - m); sum += v[i]; }
        #pragma unroll
        for (int o = 16; o; o >>= 1) sum += __shfl_xor_sync(0xffffffffu, sum, o);
        const float inv = __fdividef(1.0f, sum);

        float m2 = -1e30f;
        #pragma unroll
        for (int i = 0; i < 32; ++i) {
            float l = (alpha * srow[lane + (i << 5)] + beta * v[i] * inv) * invg;
            v[i] = l; m2 = fmaxf(m2, l);
        }
        #pragma unroll
        for (int o = 16; o; o >>= 1) m2 = fmaxf(m2, __shfl_xor_sync(0xffffffffu, m2, o));

        float s2 = 0.f;
        #pragma unroll
        for (int i = 0; i < 32; ++i) { v[i] = __expf(v[i] - m2); s2 += v[i]; }
        #pragma unroll
        for (int o = 16; o; o >>= 1) s2 += __shfl_xor_sync(0xffffffffu, s2, o);
        const float inv2 = __fdividef(1.0f, s2);

        #pragma unroll
        for (int i = 0; i < 32; ++i) grow[lane + (i << 5)] = v[i] * inv2;
    }
}

// ---------------------------------------------------------------------------
// Split + transpose: in [z][R][C] fp32 -> out hi/lo [z][C][R] bf16.
// Grid MUST be (C/32, R/32, Z): blockIdx.x -> columns, blockIdx.y -> rows.
// ---------------------------------------------------------------------------
__device__ __forceinline__ void split_transpose_body(const float* __restrict__ in,
                                                     __nv_bfloat16* __restrict__ oh,
                                                     __nv_bfloat16* __restrict__ ol,
                                                     int R, int C) {
    __shared__ float tl[32][33];
    const int c0 = blockIdx.x << 5, r0 = blockIdx.y << 5;
    const size_t zo = (size_t)blockIdx.z * R * C;
    const int tx = threadIdx.x, ty = threadIdx.y;

    #pragma unroll
    for (int i = 0; i < 4; ++i)
        tl[ty + i * 8][tx] = in[zo + (size_t)(r0 + ty + i * 8) * C + c0 + tx];
    __syncthreads();

    #pragma unroll
    for (int i = 0; i < 4; ++i) {
        float v = tl[tx][ty + i * 8];
        __nv_bfloat16 h = __float2bfloat16(v);
        __nv_bfloat16 l = __float2bfloat16(v - __bfloat162float(h));
        size_t idx = zo + (size_t)(c0 + ty + i * 8) * R + r0 + tx;
        oh[idx] = h;
        ol[idx] = l;
    }
}

__global__ void prep_W() {   // g_G (W) [bh][s][t] -> Wt [bh][t][s]
    split_transpose_body(g_G, g_Wt_hi, g_Wt_lo, S_, S_);
}
__global__ void prep_T(const float* __restrict__ tgt) {  // [b][s][e] -> Tt [b][e][s]
    split_transpose_body(tgt, g_Tt_hi, g_Tt_lo, S_, E_);
}

// ---------------------------------------------------------------------------
// Kernel D v4: split-bf16 warp-MMA output GEMM (mma.sync.m16n8k16, HMMA).
// O[bh][t][e] = sum_s W[s,t]*T[s,e]. CTA 128x128, 8 warps, k-chunk 32,
// double-buffered smem, rows padded to 40 bf16 (80 B).
// ---------------------------------------------------------------------------
#define KC_       32
#define NCHUNK_   (S_ / KC_)             // 32
#define RSTRIDE_  40                     // bf16 elems per row (80 bytes)
#define TILEB_    (128 * RSTRIDE_ * 2)   // 10240 B per 128x32 tile
#define OFF_AH_   0
#define OFF_AL_   TILEB_
#define OFF_BH_   (2 * TILEB_)
#define OFF_BL_   (3 * TILEB_)
#define BUFB_     (4 * TILEB_)           // 40960 B
#define SMEM_MMA  (2 * BUFB_)            // 81920 B

__global__ __launch_bounds__(256) void out_gemm_mma(float* __restrict__ out) {
    extern __shared__ char smem[];
    const uint32_t sb = smem_u32(smem);

    const int tid = threadIdx.x, wid = tid >> 5, lane = tid & 31;
    const int bh = blockIdx.z, b = bh >> 3;
    const int t0 = blockIdx.x << 7, e0 = blockIdx.y << 7;

    const __nv_bfloat16* WH = g_Wt_hi + ((size_t)bh * S_ + t0) * S_;
    const __nv_bfloat16* WL = g_Wt_lo + ((size_t)bh * S_ + t0) * S_;
    const __nv_bfloat16* TH = g_Tt_hi + ((size_t)b * E_ + e0) * S_;
    const __nv_bfloat16* TL = g_Tt_lo + ((size_t)b * E_ + e0) * S_;

    const int lrow = tid >> 1;
    const int lcb  = (tid & 1) << 4;            // 0 or 16
    const uint32_t so0 = (uint32_t)(lrow * (RSTRIDE_ * 2) + lcb * 2);
    const uint32_t so1 = so0 + 16;              // +8 bf16

    const int wm = (wid >> 2) * 64;
    const int wn = (wid & 3) * 32;

    float acc[4][4][4] = {};

    {
        const size_t g0 = (size_t)lrow * S_ + lcb;
        const size_t g1 = g0 + 8;
        *(uint4*)(smem + OFF_AH_ + so0) = *(const uint4*)(WH + g0);
        *(uint4*)(smem + OFF_AH_ + so1) = *(const uint4*)(WH + g1);
        *(uint4*)(smem + OFF_AL_ + so0) = *(const uint4*)(WL + g0);
        *(uint4*)(smem + OFF_AL_ + so1) = *(const uint4*)(WL + g1);
        *(uint4*)(smem + OFF_BH_ + so0) = *(const uint4*)(TH + g0);
        *(uint4*)(smem + OFF_BH_ + so1) = *(const uint4*)(TH + g1);
        *(uint4*)(smem + OFF_BL_ + so0) = *(const uint4*)(TL + g0);
        *(uint4*)(smem + OFF_BL_ + so1) = *(const uint4*)(TL + g1);
        __syncthreads();
    }

    const int a_r = lane & 15, a_c = (lane >> 4) << 3;
    const int b_r = lane & 7,  b_c = ((lane >> 3) & 1) << 3;

    for (int c = 0; c < NCHUNK_; ++c) {
        const int cur = c & 1, nxt = cur ^ 1;
        const bool have_next = (c + 1 < NCHUNK_);

        uint4 vah, vah1, val, val1, vbh, vbh1, vbl, vbl1;
        if (have_next) {
            const size_t g0 = (size_t)lrow * S_ + (size_t)(c + 1) * KC_ + lcb;
            const size_t g1 = g0 + 8;
            vah  = *(const uint4*)(WH + g0);  vah1 = *(const uint4*)(WH + g1);
            val  = *(const uint4*)(WL + g0);  val1 = *(const uint4*)(WL + g1);
            vbh  = *(const uint4*)(TH + g0);  vbh1 = *(const uint4*)(TH + g1);
            vbl  = *(const uint4*)(TL + g0);  vbl1 = *(const uint4*)(TL + g1);
        }

        const uint32_t base = sb + (uint32_t)cur * BUFB_;
        #pragma unroll
        for (int kk = 0; kk < 2; ++kk) {
            const int k0 = kk << 4;
            uint32_t Ah[4][4], Al[4][4], Bh[4][2], Bl[4][2];
            #pragma unroll
            for (int mi = 0; mi < 4; ++mi)
                ldsm_x4(Ah[mi], base + OFF_AH_ +
                        (uint32_t)((wm + mi * 16 + a_r) * (RSTRIDE_ * 2) + (a_c + k0) * 2));
            #pragma unroll
            for (int ni = 0; ni < 4; ++ni) {
                const uint32_t ro = (uint32_t)((wn + ni * 8 + b_r) * (RSTRIDE_ * 2) + (b_c + k0) * 2);
                ldsm_x2(Bh[ni], base + OFF_BH_ + ro);
                ldsm_x2(Bl[ni], base + OFF_BL_ + ro);
            }
            #pragma unroll
            for (int mi = 0; mi < 4; ++mi)
                #pragma unroll
                for (int ni = 0; ni < 4; ++ni)
                    mma16816(acc[mi][ni], Ah[mi], Bh[ni]);
            #pragma unroll
            for (int mi = 0; mi < 4; ++mi)
                #pragma unroll
                for (int ni = 0; ni < 4; ++ni)
                    mma16816(acc[mi][ni], Ah[mi], Bl[ni]);
            #pragma unroll
            for (int mi = 0; mi < 4; ++mi)
                ldsm_x4(Al[mi], base + OFF_AL_ +
                        (uint32_t)((wm + mi * 16 + a_r) * (RSTRIDE_ * 2) + (a_c + k0) * 2));
            #pragma unroll
            for (int mi = 0; mi < 4; ++mi)
                #pragma unroll
                for (int ni = 0; ni < 4; ++ni)
                    mma16816(acc[mi][ni], Al[mi], Bh[ni]);
        }

        __syncthreads();
        if (have_next) {
            char* dst = smem + nxt * BUFB_;
            *(uint4*)(dst + OFF_AH_ + so0) = vah;
            *(uint4*)(dst + OFF_AH_ + so1) = vah1;
            *(uint4*)(dst + OFF_AL_ + so0) = val;
            *(uint4*)(dst + OFF_AL_ + so1) = val1;
            *(uint4*)(dst + OFF_BH_ + so0) = vbh;
            *(uint4*)(dst + OFF_BH_ + so1) = vbh1;
            *(uint4*)(dst + OFF_BL_ + so0) = vbl;
            *(uint4*)(dst + OFF_BL_ + so1) = vbl1;
        }
        __syncthreads();
    }

    #pragma unroll
    for (int mi = 0; mi < 4; ++mi) {
        const int t = t0 + wm + mi * 16 + (lane >> 2);
        #pragma unroll
        for (int ni = 0; ni < 4; ++ni) {
            const int e = e0 + wn + ni * 8 + ((lane & 3) << 1);
            float* o = out + ((size_t)bh * S_ + t) * E_ + e;
            *(float2*)o            = make_float2(acc[mi][ni][0], acc[mi][ni][1]);
            *(float2*)(o + 8 * E_) = make_float2(acc[mi][ni][2], acc[mi][ni][3]);
        }
    }
}

// ---------------------------------------------------------------------------
extern "C" void kernel_launch(void* const* d_in, const int* in_sizes, int n_in,
                              void* d_out, int out_size) {
    (void)in_sizes; (void)n_in; (void)out_size;
    const float* src = (const float*)d_in[0];
    const float* tgt = (const float*)d_in[1];
    const float* enc = (const float*)d_in[2];
    const float* pa  = (const float*)d_in[3];
    const float* pb  = (const float*)d_in[4];
    const float* pg  = (const float*)d_in[5];
    float* out = (float*)d_out;

    cudaFuncSetAttribute(out_gemm_mma, cudaFuncAttributeMaxDynamicSharedMemorySize, SMEM_MMA);
    cudaFuncSetAttribute(scores_mma,   cudaFuncAttributeMaxDynamicSharedMemorySize, SMEM_SC);

    scan_kernel<<<BH_, D_>>>(tgt, enc);
    prep_T<<<dim3(E_ / 32, S_ / 32, B_), dim3(32, 8)>>>(tgt);   // (cols, rows, z) !
    scores_mma<<<dim3(8, 8, BH_), 256, SMEM_SC>>>(src, tgt);
    softmax_kernel<<<dim3(32, BH_), 256>>>(pa, pb, pg);
    prep_W<<<dim3(S_ / 32, S_ / 32, BH_), dim3(32, 8)>>>();
    out_gemm_mma<<<dim3(8, 4, BH_), 256, SMEM_MMA>>>(out);
}

// round 13
// speedup vs baseline: 2.8466x; 1.1791x over previous
#include <cuda_runtime.h>
#include <cuda_bf16.h>
#include <cstdint>

#define B_  4
#define S_  1024
#define E_  512
#define H_  8
#define D_  64
#define BH_ 32

// ---------------------------------------------------------------------------
// Scratch (__device__ globals; no runtime allocation allowed).
// ---------------------------------------------------------------------------
static __device__ float g_CC [(size_t)BH_ * S_ * D_];   //   8 MB [bh][t][d]
static __device__ float g_G  [(size_t)BH_ * S_ * S_];   // 128 MB [bh][s][t] grammar scores
static __device__ float g_Sem[(size_t)BH_ * S_ * S_];   // 128 MB [bh][s][t]
static __device__ __nv_bfloat16 g_Wh[(size_t)BH_ * S_ * S_];  // 64 MB [bh][s][t] W hi
static __device__ __nv_bfloat16 g_Wl[(size_t)BH_ * S_ * S_];  // 64 MB [bh][s][t] W lo

__device__ __forceinline__ float fast_tanhf(float x) {
    float e = __expf(2.0f * x);
    return 1.0f - __fdividef(2.0f, e + 1.0f);
}

__device__ __forceinline__ uint32_t smem_u32(const void* p) {
    uint32_t a;
    asm("{ .reg .u64 t; cvta.to.shared.u64 t, %1; cvt.u32.u64 %0, t; }" : "=r"(a) : "l"(p));
    return a;
}
__device__ __forceinline__ void ldsm_x4(uint32_t* r, uint32_t a) {
    asm volatile("ldmatrix.sync.aligned.m8n8.x4.shared.b16 {%0,%1,%2,%3}, [%4];"
        : "=r"(r[0]), "=r"(r[1]), "=r"(r[2]), "=r"(r[3]) : "r"(a));
}
__device__ __forceinline__ void ldsm_x2(uint32_t* r, uint32_t a) {
    asm volatile("ldmatrix.sync.aligned.m8n8.x2.shared.b16 {%0,%1}, [%2];"
        : "=r"(r[0]), "=r"(r[1]) : "r"(a));
}
__device__ __forceinline__ void ldsm_x4_t(uint32_t* r, uint32_t a) {
    asm volatile("ldmatrix.sync.aligned.m8n8.x4.trans.shared.b16 {%0,%1,%2,%3}, [%4];"
        : "=r"(r[0]), "=r"(r[1]), "=r"(r[2]), "=r"(r[3]) : "r"(a));
}
__device__ __forceinline__ void ldsm_x2_t(uint32_t* r, uint32_t a) {
    asm volatile("ldmatrix.sync.aligned.m8n8.x2.trans.shared.b16 {%0,%1}, [%2];"
        : "=r"(r[0]), "=r"(r[1]) : "r"(a));
}
__device__ __forceinline__ void mma16816(float* c, const uint32_t* a, const uint32_t* b) {
    asm volatile("mma.sync.aligned.m16n8k16.row.col.f32.bf16.bf16.f32 "
        "{%0,%1,%2,%3}, {%4,%5,%6,%7}, {%8,%9}, {%0,%1,%2,%3};"
        : "+f"(c[0]), "+f"(c[1]), "+f"(c[2]), "+f"(c[3])
        : "r"(a[0]), "r"(a[1]), "r"(a[2]), "r"(a[3]), "r"(b[0]), "r"(b[1]));
}
__device__ __forceinline__ uint32_t pack_bf16(__nv_bfloat16 a, __nv_bfloat16 b) {
    return ((uint32_t)__bfloat16_as_ushort(b) << 16) | __bfloat16_as_ushort(a);
}

// ---------------------------------------------------------------------------
// Kernel A: sequential scan.
// ---------------------------------------------------------------------------
__global__ void scan_kernel(const float* __restrict__ tgt,
                            const float* __restrict__ enc) {
    const int bh = blockIdx.x, b = bh >> 3, h = bh & 7;
    const int d = threadIdx.x;
    const float pe = enc[h * D_ + d];
    const float* kp = tgt + (size_t)b * S_ * E_ + h * D_ + d;
    float* cp = g_CC + (size_t)bh * S_ * D_ + d;
    float carry = kp[0];
    for (int t = 0; t < S_; ++t) {
        float v = fast_tanhf(carry * pe);
        cp[(size_t)t * D_] = v;
        carry = kp[(size_t)t * E_] * v;
    }
}

// ---------------------------------------------------------------------------
// Kernel B: dual score GEMM on tensor cores (split-bf16 HMMA).
// Sem = (Q.K^T)/100, G = (Q.CC^T)/8.  K-major, k = d = 64.
// ---------------------------------------------------------------------------
#define SC_RST    72
#define SC_TILEB  (128 * SC_RST * 2)   // 18432 B
#define SC_QH     0
#define SC_QL     SC_TILEB
#define SC_PH     (2 * SC_TILEB)
#define SC_PL     (3 * SC_TILEB)
#define SMEM_SC   (4 * SC_TILEB)       // 73728 B

__device__ __forceinline__ void load_split_64(const float* __restrict__ g, int gstride,
                                              char* sh, char* sl, int tid) {
    #pragma unroll
    for (int i = 0; i < 8; ++i) {
        const int q = i * 256 + tid;
        const int row = q >> 4;
        const int col = (q & 15) << 2;
        const float4 v = *(const float4*)(g + (size_t)row * gstride + col);
        const __nv_bfloat16 h0 = __float2bfloat16(v.x);
        const __nv_bfloat16 h1 = __float2bfloat16(v.y);
        const __nv_bfloat16 h2 = __float2bfloat16(v.z);
        const __nv_bfloat16 h3 = __float2bfloat16(v.w);
        const __nv_bfloat16 l0 = __float2bfloat16(v.x - __bfloat162float(h0));
        const __nv_bfloat16 l1 = __float2bfloat16(v.y - __bfloat162float(h1));
        const __nv_bfloat16 l2 = __float2bfloat16(v.z - __bfloat162float(h2));
        const __nv_bfloat16 l3 = __float2bfloat16(v.w - __bfloat162float(h3));
        const uint32_t off = (uint32_t)(row * (SC_RST * 2) + col * 2);
        *(uint2*)(sh + off) = make_uint2(pack_bf16(h0, h1), pack_bf16(h2, h3));
        *(uint2*)(sl + off) = make_uint2(pack_bf16(l0, l1), pack_bf16(l2, l3));
    }
}

__global__ __launch_bounds__(256) void scores_mma(const float* __restrict__ src,
                                                  const float* __restrict__ tgt) {
    extern __shared__ char smem[];
    const uint32_t sb = smem_u32(smem);

    const int tid = threadIdx.x, wid = tid >> 5, lane = tid & 31;
    const int bh = blockIdx.z, b = bh >> 3, h = bh & 7;
    const int s0 = blockIdx.y << 7, t0 = blockIdx.x << 7;

    load_split_64(src + ((size_t)(b * S_ + s0)) * E_ + h * D_, E_,
                  smem + SC_QH, smem + SC_QL, tid);
    load_split_64(tgt + ((size_t)(b * S_ + t0)) * E_ + h * D_, E_,
                  smem + SC_PH, smem + SC_PL, tid);
    __syncthreads();

    const int wm = (wid >> 2) * 64;
    const int wn = (wid & 3) * 32;
    const int a_r = lane & 15, a_c = (lane >> 4) << 3;
    const int b_r = lane & 7,  b_c = ((lane >> 3) & 1) << 3;

    float acc[4][4][4] = {};

    #pragma unroll
    for (int k = 0; k < 4; ++k) {
        const int k0 = k << 4;
        uint32_t Ah[4][4], Al[4][4], Bh[4][2], Bl[4][2];
        #pragma unroll
        for (int mi = 0; mi < 4; ++mi) {
            const uint32_t ro = (uint32_t)((wm + mi * 16 + a_r) * (SC_RST * 2) + (a_c + k0) * 2);
            ldsm_x4(Ah[mi], sb + SC_QH + ro);
            ldsm_x4(Al[mi], sb + SC_QL + ro);
        }
        #pragma unroll
        for (int ni = 0; ni < 4; ++ni) {
            const uint32_t ro = (uint32_t)((wn + ni * 8 + b_r) * (SC_RST * 2) + (b_c + k0) * 2);
            ldsm_x2(Bh[ni], sb + SC_PH + ro);
            ldsm_x2(Bl[ni], sb + SC_PL + ro);
        }
        #pragma unroll
        for (int mi = 0; mi < 4; ++mi)
            #pragma unroll
            for (int ni = 0; ni < 4; ++ni) {
                mma16816(acc[mi][ni], Ah[mi], Bh[ni]);
                mma16816(acc[mi][ni], Al[mi], Bh[ni]);
                mma16816(acc[mi][ni], Ah[mi], Bl[ni]);
            }
    }

    #pragma unroll
    for (int mi = 0; mi < 4; ++mi) {
        const int s = s0 + wm + mi * 16 + (lane >> 2);
        #pragma unroll
        for (int ni = 0; ni < 4; ++ni) {
            const int t = t0 + wn + ni * 8 + ((lane & 3) << 1);
            float* o = g_Sem + ((size_t)bh * S_ + s) * S_ + t;
            *(float2*)o            = make_float2(acc[mi][ni][0] * 0.01f, acc[mi][ni][1] * 0.01f);
            *(float2*)(o + 8 * S_) = make_float2(acc[mi][ni][2] * 0.01f, acc[mi][ni][3] * 0.01f);
        }
    }
    __syncthreads();

    load_split_64(g_CC + ((size_t)(bh * S_ + t0)) * D_, D_,
                  smem + SC_PH, smem + SC_PL, tid);
    __syncthreads();

    #pragma unroll
    for (int mi = 0; mi < 4; ++mi)
        #pragma unroll
        for (int ni = 0; ni < 4; ++ni)
            #pragma unroll
            for (int x = 0; x < 4; ++x)
                acc[mi][ni][x] = 0.f;

    #pragma unroll
    for (int k = 0; k < 4; ++k) {
        const int k0 = k << 4;
        uint32_t Ah[4][4], Al[4][4], Bh[4][2], Bl[4][2];
        #pragma unroll
        for (int mi = 0; mi < 4; ++mi) {
            const uint32_t ro = (uint32_t)((wm + mi * 16 + a_r) * (SC_RST * 2) + (a_c + k0) * 2);
            ldsm_x4(Ah[mi], sb + SC_QH + ro);
            ldsm_x4(Al[mi], sb + SC_QL + ro);
        }
        #pragma unroll
        for (int ni = 0; ni < 4; ++ni) {
            const uint32_t ro = (uint32_t)((wn + ni * 8 + b_r) * (SC_RST * 2) + (b_c + k0) * 2);
            ldsm_x2(Bh[ni], sb + SC_PH + ro);
            ldsm_x2(Bl[ni], sb + SC_PL + ro);
        }
        #pragma unroll
        for (int mi = 0; mi < 4; ++mi)
            #pragma unroll
            for (int ni = 0; ni < 4; ++ni) {
                mma16816(acc[mi][ni], Ah[mi], Bh[ni]);
                mma16816(acc[mi][ni], Al[mi], Bh[ni]);
                mma16816(acc[mi][ni], Ah[mi], Bl[ni]);
            }
    }

    #pragma unroll
    for (int mi = 0; mi < 4; ++mi) {
        const int s = s0 + wm + mi * 16 + (lane >> 2);
        #pragma unroll
        for (int ni = 0; ni < 4; ++ni) {
            const int t = t0 + wn + ni * 8 + ((lane & 3) << 1);
            float* o = g_G + ((size_t)bh * S_ + s) * S_ + t;
            *(float2*)o            = make_float2(acc[mi][ni][0] * 0.125f, acc[mi][ni][1] * 0.125f);
            *(float2*)(o + 8 * S_) = make_float2(acc[mi][ni][2] * 0.125f, acc[mi][ni][3] * 0.125f);
        }
    }
}

// ---------------------------------------------------------------------------
// Kernel C v2: per-row double softmax; emits W as hi/lo bf16 [s][t] directly.
// ---------------------------------------------------------------------------
__global__ __launch_bounds__(256) void softmax_kernel(const float* __restrict__ pa,
                                                      const float* __restrict__ pb,
                                                      const float* __restrict__ pg) {
    const int bh = blockIdx.y;
    const int warp = threadIdx.x >> 5, lane = threadIdx.x & 31;
    const float alpha = *pa, beta = *pb, invg = 1.0f / *pg;

    for (int rr = 0; rr < 4; ++rr) {
        const int s = (blockIdx.x << 5) + (warp << 2) + rr;
        const size_t rbase = ((size_t)bh * S_ + s) * S_;
        const float* grow = g_G + rbase;
        const float* srow = g_Sem + rbase;

        float v[32];
        float m = -1e30f;
        #pragma unroll
        for (int g = 0; g < 8; ++g) {
            const float4 x = *(const float4*)(grow + g * 128 + lane * 4);
            v[g * 4]     = x.x; v[g * 4 + 1] = x.y;
            v[g * 4 + 2] = x.z; v[g * 4 + 3] = x.w;
            m = fmaxf(fmaxf(fmaxf(m, x.x), fmaxf(x.y, x.z)), x.w);
        }
        #pragma unroll
        for (int o = 16; o; o >>= 1) m = fmaxf(m, __shfl_xor_sync(0xffffffffu, m, o));

        float sum = 0.f;
        #pragma unroll
        for (int i = 0; i < 32; ++i) { v[i] = __expf(v[i] - m); sum += v[i]; }
        #pragma unroll
        for (int o = 16; o; o >>= 1) sum += __shfl_xor_sync(0xffffffffu, sum, o);
        const float inv = __fdividef(1.0f, sum);

        float m2 = -1e30f;
        #pragma unroll
        for (int g = 0; g < 8; ++g) {
            const float4 x = *(const float4*)(srow + g * 128 + lane * 4);
            const float xs[4] = {x.x, x.y, x.z, x.w};
            #pragma unroll
            for (int j = 0; j < 4; ++j) {
                float l = (alpha * xs[j] + beta * v[g * 4 + j] * inv) * invg;
                v[g * 4 + j] = l; m2 = fmaxf(m2, l);
            }
        }
        #pragma unroll
        for (int o = 16; o; o >>= 1) m2 = fmaxf(m2, __shfl_xor_sync(0xffffffffu, m2, o));

        float s2 = 0.f;
        #pragma unroll
        for (int i = 0; i < 32; ++i) { v[i] = __expf(v[i] - m2); s2 += v[i]; }
        #pragma unroll
        for (int o = 16; o; o >>= 1) s2 += __shfl_xor_sync(0xffffffffu, s2, o);
        const float inv2 = __fdividef(1.0f, s2);

        #pragma unroll
        for (int g = 0; g < 8; ++g) {
            float w[4];
            __nv_bfloat16 h[4], l[4];
            #pragma unroll
            for (int j = 0; j < 4; ++j) {
                w[j] = v[g * 4 + j] * inv2;
                h[j] = __float2bfloat16(w[j]);
                l[j] = __float2bfloat16(w[j] - __bfloat162float(h[j]));
            }
            const size_t off = rbase + g * 128 + lane * 4;
            *(uint2*)(g_Wh + off) = make_uint2(pack_bf16(h[0], h[1]), pack_bf16(h[2], h[3]));
            *(uint2*)(g_Wl + off) = make_uint2(pack_bf16(l[0], l[1]), pack_bf16(l[2], l[3]));
        }
    }
}

// ---------------------------------------------------------------------------
// Kernel D v5: split-bf16 HMMA output GEMM via ldmatrix.trans — NO transposes.
// O[bh][t][e] = sum_s W[s][t] * T[s][e].  A = W^T (x4.trans from [s][t]),
// B = T^T (x2.trans from [s][e]). T converted fp32->hi/lo bf16 in staging.
// CTA 128(t) x 128(e), 8 warps, k-chunk 32, single-sync double buffer.
// Rows 136 bf16 (272 B): 272/16 = 17 mod 8 = 1 -> LDSM conflict-free.
// ---------------------------------------------------------------------------
#define KC_       32
#define NCHUNK_   (S_ / KC_)           // 32
#define ORST_     136                  // bf16 per smem row
#define OROWB_    (ORST_ * 2)          // 272 B
#define OTILEB_   (KC_ * OROWB_)       // 8704 B
#define OFF_WH_   0
#define OFF_WL_   OTILEB_
#define OFF_TH_   (2 * OTILEB_)
#define OFF_TL_   (3 * OTILEB_)
#define OBUFB_    (4 * OTILEB_)        // 34816 B
#define SMEM_OG   (2 * OBUFB_)         // 69632 B

__global__ __launch_bounds__(256) void out_gemm_mma(const float* __restrict__ tgt,
                                                    float* __restrict__ out) {
    extern __shared__ char smem[];
    const uint32_t sb = smem_u32(smem);

    const int tid = threadIdx.x, wid = tid >> 5, lane = tid & 31;
    const int bh = blockIdx.z, b = bh >> 3;
    const int t0 = blockIdx.x << 7, e0 = blockIdx.y << 7;

    const __nv_bfloat16* WHp = g_Wh + (size_t)bh * S_ * S_ + t0;   // row s: + s*S_
    const __nv_bfloat16* WLp = g_Wl + (size_t)bh * S_ * S_ + t0;
    const float* Tp = tgt + (size_t)b * S_ * E_ + e0;              // row s: + s*E_

    const int wq_row0 = (tid * 2) >> 4,     wq_col0 = ((tid * 2) & 15) << 3;
    const int wq_row1 = (tid * 2 + 1) >> 4, wq_col1 = ((tid * 2 + 1) & 15) << 3;

    const int wm = (wid >> 2) * 64;       // t offset 0/64
    const int wn = (wid & 3) * 32;        // e offset 0..96

    float acc[4][4][4] = {};

    uint4 rwh0, rwh1, rwl0, rwl1, rt[4];

    #define LOAD_CHUNK(sc) do {                                                    \
        rwh0 = *(const uint4*)(WHp + (size_t)((sc) + wq_row0) * S_ + wq_col0);     \
        rwh1 = *(const uint4*)(WHp + (size_t)((sc) + wq_row1) * S_ + wq_col1);     \
        rwl0 = *(const uint4*)(WLp + (size_t)((sc) + wq_row0) * S_ + wq_col0);     \
        rwl1 = *(const uint4*)(WLp + (size_t)((sc) + wq_row1) * S_ + wq_col1);     \
        _Pragma("unroll")                                                          \
        for (int j = 0; j < 4; ++j) {                                              \
            const int q = tid * 4 + j;                                             \
            rt[j] = *(const uint4*)(Tp + (size_t)((sc) + (q >> 5)) * E_ + ((q & 31) << 2)); \
        }                                                                          \
    } while (0)

    #define STORE_CHUNK(buf) do {                                                  \
        char* dst = smem + (buf) * OBUFB_;                                         \
        *(uint4*)(dst + OFF_WH_ + wq_row0 * OROWB_ + wq_col0 * 2) = rwh0;          \
        *(uint4*)(dst + OFF_WH_ + wq_row1 * OROWB_ + wq_col1 * 2) = rwh1;          \
        *(uint4*)(dst + OFF_WL_ + wq_row0 * OROWB_ + wq_col0 * 2) = rwl0;          \
        *(uint4*)(dst + OFF_WL_ + wq_row1 * OROWB_ + wq_col1 * 2) = rwl1;          \
        _Pragma("unroll")                                                          \
        for (int j = 0; j < 4; ++j) {                                              \
            const int q = tid * 4 + j;                                             \
            const int row = q >> 5, col = (q & 31) << 2;                           \
            const float4 v = *(const float4*)&rt[j];                               \
            const __nv_bfloat16 h0 = __float2bfloat16(v.x);                        \
            const __nv_bfloat16 h1 = __float2bfloat16(v.y);                        \
            const __nv_bfloat16 h2 = __float2bfloat16(v.z);                        \
            const __nv_bfloat16 h3 = __float2bfloat16(v.w);                        \
            const __nv_bfloat16 l0 = __float2bfloat16(v.x - __bfloat162float(h0)); \
            const __nv_bfloat16 l1 = __float2bfloat16(v.y - __bfloat162float(h1)); \
            const __nv_bfloat16 l2 = __float2bfloat16(v.z - __bfloat162float(h2)); \
            const __nv_bfloat16 l3 = __float2bfloat16(v.w - __bfloat162float(h3)); \
            const uint32_t off = (uint32_t)(row * OROWB_ + col * 2);               \
            *(uint2*)(dst + OFF_TH_ + off) = make_uint2(pack_bf16(h0, h1), pack_bf16(h2, h3)); \
            *(uint2*)(dst + OFF_TL_ + off) = make_uint2(pack_bf16(l0, l1), pack_bf16(l2, l3)); \
        }                                                                          \
    } while (0)

    LOAD_CHUNK(0);
    STORE_CHUNK(0);
    __syncthreads();

    const int a_s = (lane & 7) + ((lane >> 4) << 3);          // A: k-row (+8 for T2/T3)
    const int a_t = ((lane >> 3) & 1) << 3;                   // A: +8 t for T1/T3
    const int b_s = (lane & 7) + (((lane >> 3) & 1) << 3);    // B: k-row (+8 for T1)

    for (int c = 0; c < NCHUNK_; ++c) {
        const int cur = c & 1;
        const bool have_next = (c + 1 < NCHUNK_);
        if (have_next) LOAD_CHUNK((c + 1) * KC_);

        const uint32_t base = sb + (uint32_t)cur * OBUFB_;
        #pragma unroll
        for (int kk = 0; kk < 2; ++kk) {
            const int k0 = kk << 4;
            uint32_t Ah[4][4], Al[4][4], Bh[4][2], Bl[4][2];
            #pragma unroll
            for (int mi = 0; mi < 4; ++mi) {
                const uint32_t ro = (uint32_t)((k0 + a_s) * OROWB_ + (wm + mi * 16 + a_t) * 2);
                ldsm_x4_t(Ah[mi], base + OFF_WH_ + ro);
                ldsm_x4_t(Al[mi], base + OFF_WL_ + ro);
            }
            #pragma unroll
            for (int ni = 0; ni < 4; ++ni) {
                const uint32_t ro = (uint32_t)((k0 + b_s) * OROWB_ + (wn + ni * 8) * 2);
                ldsm_x2_t(Bh[ni], base + OFF_TH_ + ro);
                ldsm_x2_t(Bl[ni], base + OFF_TL_ + ro);
            }
            #pragma unroll
            for (int mi = 0; mi < 4; ++mi)
                #pragma unroll
                for (int ni = 0; ni < 4; ++ni) {
                    mma16816(acc[mi][ni], Ah[mi], Bh[ni]);
                    mma16816(acc[mi][ni], Al[mi], Bh[ni]);
                    mma16816(acc[mi][ni], Ah[mi], Bl[ni]);
                }
        }

        if (have_next) {
            STORE_CHUNK(cur ^ 1);
            __syncthreads();
        }
    }

    #pragma unroll
    for (int mi = 0; mi < 4; ++mi) {
        const int t = t0 + wm + mi * 16 + (lane >> 2);
        #pragma unroll
        for (int ni = 0; ni < 4; ++ni) {
            const int e = e0 + wn + ni * 8 + ((lane & 3) << 1);
            float* o = out + ((size_t)bh * S_ + t) * E_ + e;
            *(float2*)o            = make_float2(acc[mi][ni][0], acc[mi][ni][1]);
            *(float2*)(o + 8 * E_) = make_float2(acc[mi][ni][2], acc[mi][ni][3]);
        }
    }
    #undef LOAD_CHUNK
    #undef STORE_CHUNK
}

// ---------------------------------------------------------------------------
extern "C" void kernel_launch(void* const* d_in, const int* in_sizes, int n_in,
                              void* d_out, int out_size) {
    (void)in_sizes; (void)n_in; (void)out_size;
    const float* src = (const float*)d_in[0];
    const float* tgt = (const float*)d_in[1];
    const float* enc = (const float*)d_in[2];
    const float* pa  = (const float*)d_in[3];
    const float* pb  = (const float*)d_in[4];
    const float* pg  = (const float*)d_in[5];
    float* out = (float*)d_out;

    cudaFuncSetAttribute(scores_mma,   cudaFuncAttributeMaxDynamicSharedMemorySize, SMEM_SC);
    cudaFuncSetAttribute(out_gemm_mma, cudaFuncAttributeMaxDynamicSharedMemorySize, SMEM_OG);

    scan_kernel<<<BH_, D_>>>(tgt, enc);
    scores_mma<<<dim3(8, 8, BH_), 256, SMEM_SC>>>(src, tgt);
    softmax_kernel<<<dim3(32, BH_), 256>>>(pa, pb, pg);
    out_gemm_mma<<<dim3(8, 4, BH_), 256, SMEM_OG>>>(tgt, out);
}

// round 14
// speedup vs baseline: 3.0574x; 1.0740x over previous
#include <cuda_runtime.h>
#include <cuda_bf16.h>
#include <cstdint>

#define B_  4
#define S_  1024
#define E_  512
#define H_  8
#define D_  64
#define BH_ 32

// ---------------------------------------------------------------------------
// Scratch (__device__ globals; no runtime allocation allowed).
// ---------------------------------------------------------------------------
static __device__ float g_CC [(size_t)BH_ * S_ * D_];   //   8 MB [bh][t][d]
static __device__ float g_G  [(size_t)BH_ * S_ * S_];   // 128 MB [bh][s][t] grammar scores
static __device__ float g_Sem[(size_t)BH_ * S_ * S_];   // 128 MB [bh][s][t]
static __device__ __nv_bfloat16 g_Wh[(size_t)BH_ * S_ * S_];  // 64 MB [bh][s][t] W hi
static __device__ __nv_bfloat16 g_Wl[(size_t)BH_ * S_ * S_];  // 64 MB [bh][s][t] W lo
static __device__ __nv_bfloat16 g_Th[(size_t)B_ * S_ * E_];   //  4 MB [b][s][e] T hi
static __device__ __nv_bfloat16 g_Tl[(size_t)B_ * S_ * E_];   //  4 MB [b][s][e] T lo

__device__ __forceinline__ float fast_tanhf(float x) {
    float e = __expf(2.0f * x);
    return 1.0f - __fdividef(2.0f, e + 1.0f);
}

__device__ __forceinline__ uint32_t smem_u32(const void* p) {
    uint32_t a;
    asm("{ .reg .u64 t; cvta.to.shared.u64 t, %1; cvt.u32.u64 %0, t; }" : "=r"(a) : "l"(p));
    return a;
}
__device__ __forceinline__ void ldsm_x4(uint32_t* r, uint32_t a) {
    asm volatile("ldmatrix.sync.aligned.m8n8.x4.shared.b16 {%0,%1,%2,%3}, [%4];"
        : "=r"(r[0]), "=r"(r[1]), "=r"(r[2]), "=r"(r[3]) : "r"(a));
}
__device__ __forceinline__ void ldsm_x2(uint32_t* r, uint32_t a) {
    asm volatile("ldmatrix.sync.aligned.m8n8.x2.shared.b16 {%0,%1}, [%2];"
        : "=r"(r[0]), "=r"(r[1]) : "r"(a));
}
__device__ __forceinline__ void ldsm_x4_t(uint32_t* r, uint32_t a) {
    asm volatile("ldmatrix.sync.aligned.m8n8.x4.trans.shared.b16 {%0,%1,%2,%3}, [%4];"
        : "=r"(r[0]), "=r"(r[1]), "=r"(r[2]), "=r"(r[3]) : "r"(a));
}
__device__ __forceinline__ void ldsm_x2_t(uint32_t* r, uint32_t a) {
    asm volatile("ldmatrix.sync.aligned.m8n8.x2.trans.shared.b16 {%0,%1}, [%2];"
        : "=r"(r[0]), "=r"(r[1]) : "r"(a));
}
__device__ __forceinline__ void mma16816(float* c, const uint32_t* a, const uint32_t* b) {
    asm volatile("mma.sync.aligned.m16n8k16.row.col.f32.bf16.bf16.f32 "
        "{%0,%1,%2,%3}, {%4,%5,%6,%7}, {%8,%9}, {%0,%1,%2,%3};"
        : "+f"(c[0]), "+f"(c[1]), "+f"(c[2]), "+f"(c[3])
        : "r"(a[0]), "r"(a[1]), "r"(a[2]), "r"(a[3]), "r"(b[0]), "r"(b[1]));
}
__device__ __forceinline__ uint32_t pack_bf16(__nv_bfloat16 a, __nv_bfloat16 b) {
    return ((uint32_t)__bfloat16_as_ushort(b) << 16) | __bfloat16_as_ushort(a);
}
__device__ __forceinline__ void cp_async16(uint32_t dst, const void* src) {
    asm volatile("cp.async.cg.shared.global [%0], [%1], 16;" :: "r"(dst), "l"(src));
}
#define CP_COMMIT() asm volatile("cp.async.commit_group;" ::: "memory")
#define CP_WAIT(n)  asm volatile("cp.async.wait_group %0;" :: "n"(n) : "memory")

// ---------------------------------------------------------------------------
// Kernel A: sequential scan.
// ---------------------------------------------------------------------------
__global__ void scan_kernel(const float* __restrict__ tgt,
                            const float* __restrict__ enc) {
    const int bh = blockIdx.x, b = bh >> 3, h = bh & 7;
    const int d = threadIdx.x;
    const float pe = enc[h * D_ + d];
    const float* kp = tgt + (size_t)b * S_ * E_ + h * D_ + d;
    float* cp = g_CC + (size_t)bh * S_ * D_ + d;
    float carry = kp[0];
    for (int t = 0; t < S_; ++t) {
        float v = fast_tanhf(carry * pe);
        cp[(size_t)t * D_] = v;
        carry = kp[(size_t)t * E_] * v;
    }
}

// ---------------------------------------------------------------------------
// prep_T: target fp32 [b][s][e] -> hi/lo bf16, same layout. 2M elements.
// ---------------------------------------------------------------------------
__global__ __launch_bounds__(256) void prep_T(const float* __restrict__ tgt) {
    const size_t i4 = (size_t)blockIdx.x * 256 + threadIdx.x;   // float4 index
    const float4 v = ((const float4*)tgt)[i4];
    const __nv_bfloat16 h0 = __float2bfloat16(v.x);
    const __nv_bfloat16 h1 = __float2bfloat16(v.y);
    const __nv_bfloat16 h2 = __float2bfloat16(v.z);
    const __nv_bfloat16 h3 = __float2bfloat16(v.w);
    const __nv_bfloat16 l0 = __float2bfloat16(v.x - __bfloat162float(h0));
    const __nv_bfloat16 l1 = __float2bfloat16(v.y - __bfloat162float(h1));
    const __nv_bfloat16 l2 = __float2bfloat16(v.z - __bfloat162float(h2));
    const __nv_bfloat16 l3 = __float2bfloat16(v.w - __bfloat162float(h3));
    ((uint2*)g_Th)[i4] = make_uint2(pack_bf16(h0, h1), pack_bf16(h2, h3));
    ((uint2*)g_Tl)[i4] = make_uint2(pack_bf16(l0, l1), pack_bf16(l2, l3));
}

// ---------------------------------------------------------------------------
// Kernel B: dual score GEMM on tensor cores (split-bf16 HMMA).
// Sem = (Q.K^T)/100, G = (Q.CC^T)/8.  K-major, k = d = 64.
// ---------------------------------------------------------------------------
#define SC_RST    72
#define SC_TILEB  (128 * SC_RST * 2)   // 18432 B
#define SC_QH     0
#define SC_QL     SC_TILEB
#define SC_PH     (2 * SC_TILEB)
#define SC_PL     (3 * SC_TILEB)
#define SMEM_SC   (4 * SC_TILEB)       // 73728 B

__device__ __forceinline__ void load_split_64(const float* __restrict__ g, int gstride,
                                              char* sh, char* sl, int tid) {
    #pragma unroll
    for (int i = 0; i < 8; ++i) {
        const int q = i * 256 + tid;
        const int row = q >> 4;
        const int col = (q & 15) << 2;
        const float4 v = *(const float4*)(g + (size_t)row * gstride + col);
        const __nv_bfloat16 h0 = __float2bfloat16(v.x);
        const __nv_bfloat16 h1 = __float2bfloat16(v.y);
        const __nv_bfloat16 h2 = __float2bfloat16(v.z);
        const __nv_bfloat16 h3 = __float2bfloat16(v.w);
        const __nv_bfloat16 l0 = __float2bfloat16(v.x - __bfloat162float(h0));
        const __nv_bfloat16 l1 = __float2bfloat16(v.y - __bfloat162float(h1));
        const __nv_bfloat16 l2 = __float2bfloat16(v.z - __bfloat162float(h2));
        const __nv_bfloat16 l3 = __float2bfloat16(v.w - __bfloat162float(h3));
        const uint32_t off = (uint32_t)(row * (SC_RST * 2) + col * 2);
        *(uint2*)(sh + off) = make_uint2(pack_bf16(h0, h1), pack_bf16(h2, h3));
        *(uint2*)(sl + off) = make_uint2(pack_bf16(l0, l1), pack_bf16(l2, l3));
    }
}

__global__ __launch_bounds__(256) void scores_mma(const float* __restrict__ src,
                                                  const float* __restrict__ tgt) {
    extern __shared__ char smem[];
    const uint32_t sb = smem_u32(smem);

    const int tid = threadIdx.x, wid = tid >> 5, lane = tid & 31;
    const int bh = blockIdx.z, b = bh >> 3, h = bh & 7;
    const int s0 = blockIdx.y << 7, t0 = blockIdx.x << 7;

    load_split_64(src + ((size_t)(b * S_ + s0)) * E_ + h * D_, E_,
                  smem + SC_QH, smem + SC_QL, tid);
    load_split_64(tgt + ((size_t)(b * S_ + t0)) * E_ + h * D_, E_,
                  smem + SC_PH, smem + SC_PL, tid);
    __syncthreads();

    const int wm = (wid >> 2) * 64;
    const int wn = (wid & 3) * 32;
    const int a_r = lane & 15, a_c = (lane >> 4) << 3;
    const int b_r = lane & 7,  b_c = ((lane >> 3) & 1) << 3;

    float acc[4][4][4] = {};

    #pragma unroll
    for (int k = 0; k < 4; ++k) {
        const int k0 = k << 4;
        uint32_t Ah[4][4], Al[4][4], Bh[4][2], Bl[4][2];
        #pragma unroll
        for (int mi = 0; mi < 4; ++mi) {
            const uint32_t ro = (uint32_t)((wm + mi * 16 + a_r) * (SC_RST * 2) + (a_c + k0) * 2);
            ldsm_x4(Ah[mi], sb + SC_QH + ro);
            ldsm_x4(Al[mi], sb + SC_QL + ro);
        }
        #pragma unroll
        for (int ni = 0; ni < 4; ++ni) {
            const uint32_t ro = (uint32_t)((wn + ni * 8 + b_r) * (SC_RST * 2) + (b_c + k0) * 2);
            ldsm_x2(Bh[ni], sb + SC_PH + ro);
            ldsm_x2(Bl[ni], sb + SC_PL + ro);
        }
        #pragma unroll
        for (int mi = 0; mi < 4; ++mi)
            #pragma unroll
            for (int ni = 0; ni < 4; ++ni) {
                mma16816(acc[mi][ni], Ah[mi], Bh[ni]);
                mma16816(acc[mi][ni], Al[mi], Bh[ni]);
                mma16816(acc[mi][ni], Ah[mi], Bl[ni]);
            }
    }

    #pragma unroll
    for (int mi = 0; mi < 4; ++mi) {
        const int s = s0 + wm + mi * 16 + (lane >> 2);
        #pragma unroll
        for (int ni = 0; ni < 4; ++ni) {
            const int t = t0 + wn + ni * 8 + ((lane & 3) << 1);
            float* o = g_Sem + ((size_t)bh * S_ + s) * S_ + t;
            *(float2*)o            = make_float2(acc[mi][ni][0] * 0.01f, acc[mi][ni][1] * 0.01f);
            *(float2*)(o + 8 * S_) = make_float2(acc[mi][ni][2] * 0.01f, acc[mi][ni][3] * 0.01f);
        }
    }
    __syncthreads();

    load_split_64(g_CC + ((size_t)(bh * S_ + t0)) * D_, D_,
                  smem + SC_PH, smem + SC_PL, tid);
    __syncthreads();

    #pragma unroll
    for (int mi = 0; mi < 4; ++mi)
        #pragma unroll
        for (int ni = 0; ni < 4; ++ni)
            #pragma unroll
            for (int x = 0; x < 4; ++x)
                acc[mi][ni][x] = 0.f;

    #pragma unroll
    for (int k = 0; k < 4; ++k) {
        const int k0 = k << 4;
        uint32_t Ah[4][4], Al[4][4], Bh[4][2], Bl[4][2];
        #pragma unroll
        for (int mi = 0; mi < 4; ++mi) {
            const uint32_t ro = (uint32_t)((wm + mi * 16 + a_r) * (SC_RST * 2) + (a_c + k0) * 2);
            ldsm_x4(Ah[mi], sb + SC_QH + ro);
            ldsm_x4(Al[mi], sb + SC_QL + ro);
        }
        #pragma unroll
        for (int ni = 0; ni < 4; ++ni) {
            const uint32_t ro = (uint32_t)((wn + ni * 8 + b_r) * (SC_RST * 2) + (b_c + k0) * 2);
            ldsm_x2(Bh[ni], sb + SC_PH + ro);
            ldsm_x2(Bl[ni], sb + SC_PL + ro);
        }
        #pragma unroll
        for (int mi = 0; mi < 4; ++mi)
            #pragma unroll
            for (int ni = 0; ni < 4; ++ni) {
                mma16816(acc[mi][ni], Ah[mi], Bh[ni]);
                mma16816(acc[mi][ni], Al[mi], Bh[ni]);
                mma16816(acc[mi][ni], Ah[mi], Bl[ni]);
            }
    }

    #pragma unroll
    for (int mi = 0; mi < 4; ++mi) {
        const int s = s0 + wm + mi * 16 + (lane >> 2);
        #pragma unroll
        for (int ni = 0; ni < 4; ++ni) {
            const int t = t0 + wn + ni * 8 + ((lane & 3) << 1);
            float* o = g_G + ((size_t)bh * S_ + s) * S_ + t;
            *(float2*)o            = make_float2(acc[mi][ni][0] * 0.125f, acc[mi][ni][1] * 0.125f);
            *(float2*)(o + 8 * S_) = make_float2(acc[mi][ni][2] * 0.125f, acc[mi][ni][3] * 0.125f);
        }
    }
}

// ---------------------------------------------------------------------------
// Kernel C v2: per-row double softmax; emits W as hi/lo bf16 [s][t] directly.
// ---------------------------------------------------------------------------
__global__ __launch_bounds__(256) void softmax_kernel(const float* __restrict__ pa,
                                                      const float* __restrict__ pb,
                                                      const float* __restrict__ pg) {
    const int bh = blockIdx.y;
    const int warp = threadIdx.x >> 5, lane = threadIdx.x & 31;
    const float alpha = *pa, beta = *pb, invg = 1.0f / *pg;

    for (int rr = 0; rr < 4; ++rr) {
        const int s = (blockIdx.x << 5) + (warp << 2) + rr;
        const size_t rbase = ((size_t)bh * S_ + s) * S_;
        const float* grow = g_G + rbase;
        const float* srow = g_Sem + rbase;

        float v[32];
        float m = -1e30f;
        #pragma unroll
        for (int g = 0; g < 8; ++g) {
            const float4 x = *(const float4*)(grow + g * 128 + lane * 4);
            v[g * 4]     = x.x; v[g * 4 + 1] = x.y;
            v[g * 4 + 2] = x.z; v[g * 4 + 3] = x.w;
            m = fmaxf(fmaxf(fmaxf(m, x.x), fmaxf(x.y, x.z)), x.w);
        }
        #pragma unroll
        for (int o = 16; o; o >>= 1) m = fmaxf(m, __shfl_xor_sync(0xffffffffu, m, o));

        float sum = 0.f;
        #pragma unroll
        for (int i = 0; i < 32; ++i) { v[i] = __expf(v[i] - m); sum += v[i]; }
        #pragma unroll
        for (int o = 16; o; o >>= 1) sum += __shfl_xor_sync(0xffffffffu, sum, o);
        const float inv = __fdividef(1.0f, sum);

        float m2 = -1e30f;
        #pragma unroll
        for (int g = 0; g < 8; ++g) {
            const float4 x = *(const float4*)(srow + g * 128 + lane * 4);
            const float xs[4] = {x.x, x.y, x.z, x.w};
            #pragma unroll
            for (int j = 0; j < 4; ++j) {
                float l = (alpha * xs[j] + beta * v[g * 4 + j] * inv) * invg;
                v[g * 4 + j] = l; m2 = fmaxf(m2, l);
            }
        }
        #pragma unroll
        for (int o = 16; o; o >>= 1) m2 = fmaxf(m2, __shfl_xor_sync(0xffffffffu, m2, o));

        float s2 = 0.f;
        #pragma unroll
        for (int i = 0; i < 32; ++i) { v[i] = __expf(v[i] - m2); s2 += v[i]; }
        #pragma unroll
        for (int o = 16; o; o >>= 1) s2 += __shfl_xor_sync(0xffffffffu, s2, o);
        const float inv2 = __fdividef(1.0f, s2);

        #pragma unroll
        for (int g = 0; g < 8; ++g) {
            float w[4];
            __nv_bfloat16 h[4], l[4];
            #pragma unroll
            for (int j = 0; j < 4; ++j) {
                w[j] = v[g * 4 + j] * inv2;
                h[j] = __float2bfloat16(w[j]);
                l[j] = __float2bfloat16(w[j] - __bfloat162float(h[j]));
            }
            const size_t off = rbase + g * 128 + lane * 4;
            *(uint2*)(g_Wh + off) = make_uint2(pack_bf16(h[0], h[1]), pack_bf16(h[2], h[3]));
            *(uint2*)(g_Wl + off) = make_uint2(pack_bf16(l[0], l[1]), pack_bf16(l[2], l[3]));
        }
    }
}

// ---------------------------------------------------------------------------
// Kernel D v6: split-bf16 HMMA output GEMM, cp.async pipeline, 2 CTAs/SM.
// O[bh][t][e] = sum_s W[s][t] * T[s][e]. All 4 tiles stream via cp.async.cg;
// no in-loop conversion, no staging registers.
// CTA 128(t) x 128(e), 8 warps, k-chunk 32, double-buffered.
// ---------------------------------------------------------------------------
#define KC_       32
#define NCHUNK_   (S_ / KC_)           // 32
#define ORST_     136                  // bf16 per smem row
#define OROWB_    (ORST_ * 2)          // 272 B
#define OTILEB_   (KC_ * OROWB_)       // 8704 B
#define OFF_WH_   0
#define OFF_WL_   OTILEB_
#define OFF_TH_   (2 * OTILEB_)
#define OFF_TL_   (3 * OTILEB_)
#define OBUFB_    (4 * OTILEB_)        // 34816 B
#define SMEM_OG   (2 * OBUFB_)         // 69632 B

__global__ __launch_bounds__(256, 2) void out_gemm_mma(float* __restrict__ out) {
    extern __shared__ char smem[];
    const uint32_t sb = smem_u32(smem);

    const int tid = threadIdx.x, wid = tid >> 5, lane = tid & 31;
    const int bh = blockIdx.z, b = bh >> 3;
    const int t0 = blockIdx.x << 7, e0 = blockIdx.y << 7;

    const __nv_bfloat16* WHp = g_Wh + (size_t)bh * S_ * S_ + t0;   // + s*S_
    const __nv_bfloat16* WLp = g_Wl + (size_t)bh * S_ * S_ + t0;
    const __nv_bfloat16* THp = g_Th + (size_t)b * S_ * E_ + e0;    // + s*E_
    const __nv_bfloat16* TLp = g_Tl + (size_t)b * S_ * E_ + e0;

    const int wm = (wid >> 2) * 64;       // t offset 0/64
    const int wn = (wid & 3) * 32;        // e offset 0..96

    // cp.async mapping: 2 quads/thread/tile; row = q>>4 (0..31), col = (q&15)*8.
    const int q0r = (tid * 2) >> 4,       q0c = ((tid * 2) & 15) << 3;
    const int q1r = (tid * 2 + 1) >> 4,   q1c = ((tid * 2 + 1) & 15) << 3;

    #define ISSUE_CHUNK(sc, buf) do {                                              \
        const uint32_t db = sb + (uint32_t)(buf) * OBUFB_;                         \
        const uint32_t o0 = (uint32_t)(q0r * OROWB_ + q0c * 2);                    \
        const uint32_t o1 = (uint32_t)(q1r * OROWB_ + q1c * 2);                    \
        const size_t gw0 = (size_t)((sc) + q0r) * S_ + q0c;                        \
        const size_t gw1 = (size_t)((sc) + q1r) * S_ + q1c;                        \
        const size_t gt0 = (size_t)((sc) + q0r) * E_ + q0c;                        \
        const size_t gt1 = (size_t)((sc) + q1r) * E_ + q1c;                        \
        cp_async16(db + OFF_WH_ + o0, WHp + gw0);                                  \
        cp_async16(db + OFF_WH_ + o1, WHp + gw1);                                  \
        cp_async16(db + OFF_WL_ + o0, WLp + gw0);                                  \
        cp_async16(db + OFF_WL_ + o1, WLp + gw1);                                  \
        cp_async16(db + OFF_TH_ + o0, THp + gt0);                                  \
        cp_async16(db + OFF_TH_ + o1, THp + gt1);                                  \
        cp_async16(db + OFF_TL_ + o0, TLp + gt0);                                  \
        cp_async16(db + OFF_TL_ + o1, TLp + gt1);                                  \
        CP_COMMIT();                                                               \
    } while (0)

    float acc[4][4][4] = {};

    ISSUE_CHUNK(0, 0);

    // ldmatrix.trans lane address components (verified R13).
    const int a_s = (lane & 7) + ((lane >> 4) << 3);
    const int a_t = ((lane >> 3) & 1) << 3;
    const int b_s = (lane & 7) + (((lane >> 3) & 1) << 3);

    for (int c = 0; c < NCHUNK_; ++c) {
        const int cur = c & 1;
        const bool have_next = (c + 1 < NCHUNK_);
        if (have_next) {
            ISSUE_CHUNK((c + 1) * KC_, cur ^ 1);
            CP_WAIT(1);
        } else {
            CP_WAIT(0);
        }
        __syncthreads();

        const uint32_t base = sb + (uint32_t)cur * OBUFB_;
        #pragma unroll
        for (int kk = 0; kk < 2; ++kk) {
            const int k0 = kk << 4;
            uint32_t Ah[4][4], Al[4][4], Bh[4][2], Bl[4][2];
            #pragma unroll
            for (int mi = 0; mi < 4; ++mi) {
                const uint32_t ro = (uint32_t)((k0 + a_s) * OROWB_ + (wm + mi * 16 + a_t) * 2);
                ldsm_x4_t(Ah[mi], base + OFF_WH_ + ro);
            }
            #pragma unroll
            for (int ni = 0; ni < 4; ++ni) {
                const uint32_t ro = (uint32_t)((k0 + b_s) * OROWB_ + (wn + ni * 8) * 2);
                ldsm_x2_t(Bh[ni], base + OFF_TH_ + ro);
            }
            #pragma unroll
            for (int mi = 0; mi < 4; ++mi)
                #pragma unroll
                for (int ni = 0; ni < 4; ++ni)
                    mma16816(acc[mi][ni], Ah[mi], Bh[ni]);
            #pragma unroll
            for (int ni = 0; ni < 4; ++ni) {
                const uint32_t ro = (uint32_t)((k0 + b_s) * OROWB_ + (wn + ni * 8) * 2);
                ldsm_x2_t(Bl[ni], base + OFF_TL_ + ro);
            }
            #pragma unroll
            for (int mi = 0; mi < 4; ++mi)
                #pragma unroll
                for (int ni = 0; ni < 4; ++ni)
                    mma16816(acc[mi][ni], Ah[mi], Bl[ni]);
            #pragma unroll
            for (int mi = 0; mi < 4; ++mi) {
                const uint32_t ro = (uint32_t)((k0 + a_s) * OROWB_ + (wm + mi * 16 + a_t) * 2);
                ldsm_x4_t(Al[mi], base + OFF_WL_ + ro);
            }
            #pragma unroll
            for (int mi = 0; mi < 4; ++mi)
                #pragma unroll
                for (int ni = 0; ni < 4; ++ni)
                    mma16816(acc[mi][ni], Al[mi], Bh[ni]);
        }

        __syncthreads();   // all warps done with buffer `cur` before c+2 refill
    }

    #pragma unroll
    for (int mi = 0; mi < 4; ++mi) {
        const int t = t0 + wm + mi * 16 + (lane >> 2);
        #pragma unroll
        for (int ni = 0; ni < 4; ++ni) {
            const int e = e0 + wn + ni * 8 + ((lane & 3) << 1);
            float* o = out + ((size_t)bh * S_ + t) * E_ + e;
            *(float2*)o            = make_float2(acc[mi][ni][0], acc[mi][ni][1]);
            *(float2*)(o + 8 * E_) = make_float2(acc[mi][ni][2], acc[mi][ni][3]);
        }
    }
    #undef ISSUE_CHUNK
}

// ---------------------------------------------------------------------------
extern "C" void kernel_launch(void* const* d_in, const int* in_sizes, int n_in,
                              void* d_out, int out_size) {
    (void)in_sizes; (void)n_in; (void)out_size;
    const float* src = (const float*)d_in[0];
    const float* tgt = (const float*)d_in[1];
    const float* enc = (const float*)d_in[2];
    const float* pa  = (const float*)d_in[3];
    const float* pb  = (const float*)d_in[4];
    const float* pg  = (const float*)d_in[5];
    float* out = (float*)d_out;

    cudaFuncSetAttribute(scores_mma,   cudaFuncAttributeMaxDynamicSharedMemorySize, SMEM_SC);
    cudaFuncSetAttribute(out_gemm_mma, cudaFuncAttributeMaxDynamicSharedMemorySize, SMEM_OG);

    scan_kernel<<<BH_, D_>>>(tgt, enc);
    prep_T<<<(B_ * S_ * E_) / 4 / 256, 256>>>(tgt);
    scores_mma<<<dim3(8, 8, BH_), 256, SMEM_SC>>>(src, tgt);
    softmax_kernel<<<dim3(32, BH_), 256>>>(pa, pb, pg);
    out_gemm_mma<<<dim3(8, 4, BH_), 256, SMEM_OG>>>(out);
}

// round 15
// speedup vs baseline: 3.2377x; 1.0590x over previous
#include <cuda_runtime.h>
#include <cuda_bf16.h>
#include <cstdint>

#define B_  4
#define S_  1024
#define E_  512
#define H_  8
#define D_  64
#define BH_ 32

// ---------------------------------------------------------------------------
// Scratch (__device__ globals; no runtime allocation allowed).
// ---------------------------------------------------------------------------
static __device__ float g_CC [(size_t)BH_ * S_ * D_];   //   8 MB [bh][t][d]
static __device__ float g_G  [(size_t)BH_ * S_ * S_];   // 128 MB [bh][s][t] grammar scores
static __device__ float g_Sem[(size_t)BH_ * S_ * S_];   // 128 MB [bh][s][t]
static __device__ __nv_bfloat16 g_Wh[(size_t)BH_ * S_ * S_];  // 64 MB [bh][s][t] W hi
static __device__ __nv_bfloat16 g_Wl[(size_t)BH_ * S_ * S_];  // 64 MB [bh][s][t] W lo
static __device__ __nv_bfloat16 g_Th[(size_t)B_ * S_ * E_];   //  4 MB [b][s][e] T hi
static __device__ __nv_bfloat16 g_Tl[(size_t)B_ * S_ * E_];   //  4 MB [b][s][e] T lo

__device__ __forceinline__ float fast_tanhf(float x) {
    float e = __expf(2.0f * x);
    return 1.0f - __fdividef(2.0f, e + 1.0f);
}

__device__ __forceinline__ uint32_t smem_u32(const void* p) {
    uint32_t a;
    asm("{ .reg .u64 t; cvta.to.shared.u64 t, %1; cvt.u32.u64 %0, t; }" : "=r"(a) : "l"(p));
    return a;
}
__device__ __forceinline__ void ldsm_x4(uint32_t* r, uint32_t a) {
    asm volatile("ldmatrix.sync.aligned.m8n8.x4.shared.b16 {%0,%1,%2,%3}, [%4];"
        : "=r"(r[0]), "=r"(r[1]), "=r"(r[2]), "=r"(r[3]) : "r"(a));
}
__device__ __forceinline__ void ldsm_x2(uint32_t* r, uint32_t a) {
    asm volatile("ldmatrix.sync.aligned.m8n8.x2.shared.b16 {%0,%1}, [%2];"
        : "=r"(r[0]), "=r"(r[1]) : "r"(a));
}
__device__ __forceinline__ void ldsm_x4_t(uint32_t* r, uint32_t a) {
    asm volatile("ldmatrix.sync.aligned.m8n8.x4.trans.shared.b16 {%0,%1,%2,%3}, [%4];"
        : "=r"(r[0]), "=r"(r[1]), "=r"(r[2]), "=r"(r[3]) : "r"(a));
}
__device__ __forceinline__ void ldsm_x2_t(uint32_t* r, uint32_t a) {
    asm volatile("ldmatrix.sync.aligned.m8n8.x2.trans.shared.b16 {%0,%1}, [%2];"
        : "=r"(r[0]), "=r"(r[1]) : "r"(a));
}
__device__ __forceinline__ void mma16816(float* c, const uint32_t* a, const uint32_t* b) {
    asm volatile("mma.sync.aligned.m16n8k16.row.col.f32.bf16.bf16.f32 "
        "{%0,%1,%2,%3}, {%4,%5,%6,%7}, {%8,%9}, {%0,%1,%2,%3};"
        : "+f"(c[0]), "+f"(c[1]), "+f"(c[2]), "+f"(c[3])
        : "r"(a[0]), "r"(a[1]), "r"(a[2]), "r"(a[3]), "r"(b[0]), "r"(b[1]));
}
__device__ __forceinline__ uint32_t pack_bf16(__nv_bfloat16 a, __nv_bfloat16 b) {
    return ((uint32_t)__bfloat16_as_ushort(b) << 16) | __bfloat16_as_ushort(a);
}
__device__ __forceinline__ void cp_async16(uint32_t dst, const void* src) {
    asm volatile("cp.async.cg.shared.global [%0], [%1], 16;" :: "r"(dst), "l"(src));
}
#define CP_COMMIT() asm volatile("cp.async.commit_group;" ::: "memory")
#define CP_WAIT(n)  asm volatile("cp.async.wait_group %0;" :: "n"(n) : "memory")

// ---------------------------------------------------------------------------
// Kernel A: sequential scan.
// ---------------------------------------------------------------------------
__global__ void scan_kernel(const float* __restrict__ tgt,
                            const float* __restrict__ enc) {
    const int bh = blockIdx.x, b = bh >> 3, h = bh & 7;
    const int d = threadIdx.x;
    const float pe = enc[h * D_ + d];
    const float* kp = tgt + (size_t)b * S_ * E_ + h * D_ + d;
    float* cp = g_CC + (size_t)bh * S_ * D_ + d;
    float carry = kp[0];
    for (int t = 0; t < S_; ++t) {
        float v = fast_tanhf(carry * pe);
        cp[(size_t)t * D_] = v;
        carry = kp[(size_t)t * E_] * v;
    }
}

// ---------------------------------------------------------------------------
// prep_T: target fp32 [b][s][e] -> hi/lo bf16, same layout.
// ---------------------------------------------------------------------------
__global__ __launch_bounds__(256) void prep_T(const float* __restrict__ tgt) {
    const size_t i4 = (size_t)blockIdx.x * 256 + threadIdx.x;
    const float4 v = ((const float4*)tgt)[i4];
    const __nv_bfloat16 h0 = __float2bfloat16(v.x);
    const __nv_bfloat16 h1 = __float2bfloat16(v.y);
    const __nv_bfloat16 h2 = __float2bfloat16(v.z);
    const __nv_bfloat16 h3 = __float2bfloat16(v.w);
    const __nv_bfloat16 l0 = __float2bfloat16(v.x - __bfloat162float(h0));
    const __nv_bfloat16 l1 = __float2bfloat16(v.y - __bfloat162float(h1));
    const __nv_bfloat16 l2 = __float2bfloat16(v.z - __bfloat162float(h2));
    const __nv_bfloat16 l3 = __float2bfloat16(v.w - __bfloat162float(h3));
    ((uint2*)g_Th)[i4] = make_uint2(pack_bf16(h0, h1), pack_bf16(h2, h3));
    ((uint2*)g_Tl)[i4] = make_uint2(pack_bf16(l0, l1), pack_bf16(l2, l3));
}

// ---------------------------------------------------------------------------
// Kernel B v3: score GEMM, ONE pass per CTA (grid.z = 2*BH).
// even z: Sem = (Q.K^T)/100 ; odd z: G = (Q.CC^T)/8.
// ---------------------------------------------------------------------------
#define SC_RST    72
#define SC_TILEB  (128 * SC_RST * 2)   // 18432 B
#define SC_QH     0
#define SC_QL     SC_TILEB
#define SC_PH     (2 * SC_TILEB)
#define SC_PL     (3 * SC_TILEB)
#define SMEM_SC   (4 * SC_TILEB)       // 73728 B

__device__ __forceinline__ void load_split_64(const float* __restrict__ g, int gstride,
                                              char* sh, char* sl, int tid) {
    #pragma unroll
    for (int i = 0; i < 8; ++i) {
        const int q = i * 256 + tid;
        const int row = q >> 4;
        const int col = (q & 15) << 2;
        const float4 v = *(const float4*)(g + (size_t)row * gstride + col);
        const __nv_bfloat16 h0 = __float2bfloat16(v.x);
        const __nv_bfloat16 h1 = __float2bfloat16(v.y);
        const __nv_bfloat16 h2 = __float2bfloat16(v.z);
        const __nv_bfloat16 h3 = __float2bfloat16(v.w);
        const __nv_bfloat16 l0 = __float2bfloat16(v.x - __bfloat162float(h0));
        const __nv_bfloat16 l1 = __float2bfloat16(v.y - __bfloat162float(h1));
        const __nv_bfloat16 l2 = __float2bfloat16(v.z - __bfloat162float(h2));
        const __nv_bfloat16 l3 = __float2bfloat16(v.w - __bfloat162float(h3));
        const uint32_t off = (uint32_t)(row * (SC_RST * 2) + col * 2);
        *(uint2*)(sh + off) = make_uint2(pack_bf16(h0, h1), pack_bf16(h2, h3));
        *(uint2*)(sl + off) = make_uint2(pack_bf16(l0, l1), pack_bf16(l2, l3));
    }
}

__global__ __launch_bounds__(256, 2) void scores_mma(const float* __restrict__ src,
                                                     const float* __restrict__ tgt) {
    extern __shared__ char smem[];
    const uint32_t sb = smem_u32(smem);

    const int tid = threadIdx.x, wid = tid >> 5, lane = tid & 31;
    const int zz = blockIdx.z;
    const int bh = zz >> 1, pass = zz & 1;
    const int b = bh >> 3, h = bh & 7;
    const int s0 = blockIdx.y << 7, t0 = blockIdx.x << 7;

    // Stage Q tile.
    load_split_64(src + ((size_t)(b * S_ + s0)) * E_ + h * D_, E_,
                  smem + SC_QH, smem + SC_QL, tid);
    // Stage B-operand tile: K (pass 0) or CC (pass 1).
    if (pass == 0)
        load_split_64(tgt + ((size_t)(b * S_ + t0)) * E_ + h * D_, E_,
                      smem + SC_PH, smem + SC_PL, tid);
    else
        load_split_64(g_CC + ((size_t)(bh * S_ + t0)) * D_, D_,
                      smem + SC_PH, smem + SC_PL, tid);
    __syncthreads();

    const int wm = (wid >> 2) * 64;
    const int wn = (wid & 3) * 32;
    const int a_r = lane & 15, a_c = (lane >> 4) << 3;
    const int b_r = lane & 7,  b_c = ((lane >> 3) & 1) << 3;

    float acc[4][4][4] = {};

    #pragma unroll
    for (int k = 0; k < 4; ++k) {
        const int k0 = k << 4;
        uint32_t Ah[4][4], Al[4][4], Bh[4][2], Bl[4][2];
        #pragma unroll
        for (int mi = 0; mi < 4; ++mi) {
            const uint32_t ro = (uint32_t)((wm + mi * 16 + a_r) * (SC_RST * 2) + (a_c + k0) * 2);
            ldsm_x4(Ah[mi], sb + SC_QH + ro);
            ldsm_x4(Al[mi], sb + SC_QL + ro);
        }
        #pragma unroll
        for (int ni = 0; ni < 4; ++ni) {
            const uint32_t ro = (uint32_t)((wn + ni * 8 + b_r) * (SC_RST * 2) + (b_c + k0) * 2);
            ldsm_x2(Bh[ni], sb + SC_PH + ro);
            ldsm_x2(Bl[ni], sb + SC_PL + ro);
        }
        #pragma unroll
        for (int mi = 0; mi < 4; ++mi)
            #pragma unroll
            for (int ni = 0; ni < 4; ++ni) {
                mma16816(acc[mi][ni], Ah[mi], Bh[ni]);
                mma16816(acc[mi][ni], Al[mi], Bh[ni]);
                mma16816(acc[mi][ni], Ah[mi], Bl[ni]);
            }
    }

    const float scale = pass ? 0.125f : 0.01f;
    float* dst = (pass ? g_G : g_Sem) + ((size_t)bh * S_) * S_;
    #pragma unroll
    for (int mi = 0; mi < 4; ++mi) {
        const int s = s0 + wm + mi * 16 + (lane >> 2);
        #pragma unroll
        for (int ni = 0; ni < 4; ++ni) {
            const int t = t0 + wn + ni * 8 + ((lane & 3) << 1);
            float* o = dst + (size_t)s * S_ + t;
            *(float2*)o            = make_float2(acc[mi][ni][0] * scale, acc[mi][ni][1] * scale);
            *(float2*)(o + 8 * S_) = make_float2(acc[mi][ni][2] * scale, acc[mi][ni][3] * scale);
        }
    }
}

// ---------------------------------------------------------------------------
// Kernel C: per-row double softmax; emits W as hi/lo bf16 [s][t] directly.
// ---------------------------------------------------------------------------
__global__ __launch_bounds__(256) void softmax_kernel(const float* __restrict__ pa,
                                                      const float* __restrict__ pb,
                                                      const float* __restrict__ pg) {
    const int bh = blockIdx.y;
    const int warp = threadIdx.x >> 5, lane = threadIdx.x & 31;
    const float alpha = *pa, beta = *pb, invg = 1.0f / *pg;

    for (int rr = 0; rr < 4; ++rr) {
        const int s = (blockIdx.x << 5) + (warp << 2) + rr;
        const size_t rbase = ((size_t)bh * S_ + s) * S_;
        const float* grow = g_G + rbase;
        const float* srow = g_Sem + rbase;

        float v[32];
        float m = -1e30f;
        #pragma unroll
        for (int g = 0; g < 8; ++g) {
            const float4 x = *(const float4*)(grow + g * 128 + lane * 4);
            v[g * 4]     = x.x; v[g * 4 + 1] = x.y;
            v[g * 4 + 2] = x.z; v[g * 4 + 3] = x.w;
            m = fmaxf(fmaxf(fmaxf(m, x.x), fmaxf(x.y, x.z)), x.w);
        }
        #pragma unroll
        for (int o = 16; o; o >>= 1) m = fmaxf(m, __shfl_xor_sync(0xffffffffu, m, o));

        float sum = 0.f;
        #pragma unroll
        for (int i = 0; i < 32; ++i) { v[i] = __expf(v[i] - m); sum += v[i]; }
        #pragma unroll
        for (int o = 16; o; o >>= 1) sum += __shfl_xor_sync(0xffffffffu, sum, o);
        const float inv = __fdividef(1.0f, sum);

        float m2 = -1e30f;
        #pragma unroll
        for (int g = 0; g < 8; ++g) {
            const float4 x = *(const float4*)(srow + g * 128 + lane * 4);
            const float xs[4] = {x.x, x.y, x.z, x.w};
            #pragma unroll
            for (int j = 0; j < 4; ++j) {
                float l = (alpha * xs[j] + beta * v[g * 4 + j] * inv) * invg;
                v[g * 4 + j] = l; m2 = fmaxf(m2, l);
            }
        }
        #pragma unroll
        for (int o = 16; o; o >>= 1) m2 = fmaxf(m2, __shfl_xor_sync(0xffffffffu, m2, o));

        float s2 = 0.f;
        #pragma unroll
        for (int i = 0; i < 32; ++i) { v[i] = __expf(v[i] - m2); s2 += v[i]; }
        #pragma unroll
        for (int o = 16; o; o >>= 1) s2 += __shfl_xor_sync(0xffffffffu, s2, o);
        const float inv2 = __fdividef(1.0f, s2);

        #pragma unroll
        for (int g = 0; g < 8; ++g) {
            float w[4];
            __nv_bfloat16 h[4], l[4];
            #pragma unroll
            for (int j = 0; j < 4; ++j) {
                w[j] = v[g * 4 + j] * inv2;
                h[j] = __float2bfloat16(w[j]);
                l[j] = __float2bfloat16(w[j] - __bfloat162float(h[j]));
            }
            const size_t off = rbase + g * 128 + lane * 4;
            *(uint2*)(g_Wh + off) = make_uint2(pack_bf16(h[0], h[1]), pack_bf16(h[2], h[3]));
            *(uint2*)(g_Wl + off) = make_uint2(pack_bf16(l[0], l[1]), pack_bf16(l[2], l[3]));
        }
    }
}

// ---------------------------------------------------------------------------
// Kernel D v7: split-bf16 HMMA output GEMM, 3-stage cp.async pipeline,
// ONE __syncthreads per chunk, 2 CTAs/SM.
// ---------------------------------------------------------------------------
#define KC_       32
#define NCHUNK_   (S_ / KC_)           // 32
#define NSTAGE_   3
#define ORST_     136                  // bf16 per smem row
#define OROWB_    (ORST_ * 2)          // 272 B
#define OTILEB_   (KC_ * OROWB_)       // 8704 B
#define OFF_WH_   0
#define OFF_WL_   OTILEB_
#define OFF_TH_   (2 * OTILEB_)
#define OFF_TL_   (3 * OTILEB_)
#define OBUFB_    (4 * OTILEB_)        // 34816 B
#define SMEM_OG   (NSTAGE_ * OBUFB_)   // 104448 B

__global__ __launch_bounds__(256, 2) void out_gemm_mma(float* __restrict__ out) {
    extern __shared__ char smem[];
    const uint32_t sb = smem_u32(smem);

    const int tid = threadIdx.x, wid = tid >> 5, lane = tid & 31;
    const int bh = blockIdx.z, b = bh >> 3;
    const int t0 = blockIdx.x << 7, e0 = blockIdx.y << 7;

    const __nv_bfloat16* WHp = g_Wh + (size_t)bh * S_ * S_ + t0;   // + s*S_
    const __nv_bfloat16* WLp = g_Wl + (size_t)bh * S_ * S_ + t0;
    const __nv_bfloat16* THp = g_Th + (size_t)b * S_ * E_ + e0;    // + s*E_
    const __nv_bfloat16* TLp = g_Tl + (size_t)b * S_ * E_ + e0;

    const int wm = (wid >> 2) * 64;       // t offset 0/64
    const int wn = (wid & 3) * 32;        // e offset 0..96

    const int q0r = (tid * 2) >> 4,       q0c = ((tid * 2) & 15) << 3;
    const int q1r = (tid * 2 + 1) >> 4,   q1c = ((tid * 2 + 1) & 15) << 3;

    #define ISSUE_CHUNK(sc, buf) do {                                              \
        const uint32_t db = sb + (uint32_t)(buf) * OBUFB_;                         \
        const uint32_t o0 = (uint32_t)(q0r * OROWB_ + q0c * 2);                    \
        const uint32_t o1 = (uint32_t)(q1r * OROWB_ + q1c * 2);                    \
        const size_t gw0 = (size_t)((sc) + q0r) * S_ + q0c;                        \
        const size_t gw1 = (size_t)((sc) + q1r) * S_ + q1c;                        \
        const size_t gt0 = (size_t)((sc) + q0r) * E_ + q0c;                        \
        const size_t gt1 = (size_t)((sc) + q1r) * E_ + q1c;                        \
        cp_async16(db + OFF_WH_ + o0, WHp + gw0);                                  \
        cp_async16(db + OFF_WH_ + o1, WHp + gw1);                                  \
        cp_async16(db + OFF_WL_ + o0, WLp + gw0);                                  \
        cp_async16(db + OFF_WL_ + o1, WLp + gw1);                                  \
        cp_async16(db + OFF_TH_ + o0, THp + gt0);                                  \
        cp_async16(db + OFF_TH_ + o1, THp + gt1);                                  \
        cp_async16(db + OFF_TL_ + o0, TLp + gt0);                                  \
        cp_async16(db + OFF_TL_ + o1, TLp + gt1);                                  \
        CP_COMMIT();                                                               \
    } while (0)

    float acc[4][4][4] = {};

    ISSUE_CHUNK(0, 0);
    ISSUE_CHUNK(KC_, 1);

    const int a_s = (lane & 7) + ((lane >> 4) << 3);
    const int a_t = ((lane >> 3) & 1) << 3;
    const int b_s = (lane & 7) + (((lane >> 3) & 1) << 3);

    int buf = 0;
    for (int c = 0; c < NCHUNK_; ++c) {
        if (c == NCHUNK_ - 1) { CP_WAIT(0); } else { CP_WAIT(1); }
        __syncthreads();   // chunk c visible to all; all reads of buf (from c-NSTAGE_+... ) done

        if (c + 2 < NCHUNK_) {
            int nb = buf + 2; if (nb >= NSTAGE_) nb -= NSTAGE_;
            ISSUE_CHUNK((c + 2) * KC_, nb);
        }

        const uint32_t base = sb + (uint32_t)buf * OBUFB_;
        #pragma unroll
        for (int kk = 0; kk < 2; ++kk) {
            const int k0 = kk << 4;
            uint32_t Ah[4][4], Al[4][4], Bh[4][2], Bl[4][2];
            #pragma unroll
            for (int mi = 0; mi < 4; ++mi) {
                const uint32_t ro = (uint32_t)((k0 + a_s) * OROWB_ + (wm + mi * 16 + a_t) * 2);
                ldsm_x4_t(Ah[mi], base + OFF_WH_ + ro);
            }
            #pragma unroll
            for (int ni = 0; ni < 4; ++ni) {
                const uint32_t ro = (uint32_t)((k0 + b_s) * OROWB_ + (wn + ni * 8) * 2);
                ldsm_x2_t(Bh[ni], base + OFF_TH_ + ro);
            }
            #pragma unroll
            for (int mi = 0; mi < 4; ++mi)
                #pragma unroll
                for (int ni = 0; ni < 4; ++ni)
                    mma16816(acc[mi][ni], Ah[mi], Bh[ni]);
            #pragma unroll
            for (int ni = 0; ni < 4; ++ni) {
                const uint32_t ro = (uint32_t)((k0 + b_s) * OROWB_ + (wn + ni * 8) * 2);
                ldsm_x2_t(Bl[ni], base + OFF_TL_ + ro);
            }
            #pragma unroll
            for (int mi = 0; mi < 4; ++mi)
                #pragma unroll
                for (int ni = 0; ni < 4; ++ni)
                    mma16816(acc[mi][ni], Ah[mi], Bl[ni]);
            #pragma unroll
            for (int mi = 0; mi < 4; ++mi) {
                const uint32_t ro = (uint32_t)((k0 + a_s) * OROWB_ + (wm + mi * 16 + a_t) * 2);
                ldsm_x4_t(Al[mi], base + OFF_WL_ + ro);
            }
            #pragma unroll
            for (int mi = 0; mi < 4; ++mi)
                #pragma unroll
                for (int ni = 0; ni < 4; ++ni)
                    mma16816(acc[mi][ni], Al[mi], Bh[ni]);
        }

        if (++buf == NSTAGE_) buf = 0;
    }

    #pragma unroll
    for (int mi = 0; mi < 4; ++mi) {
        const int t = t0 + wm + mi * 16 + (lane >> 2);
        #pragma unroll
        for (int ni = 0; ni < 4; ++ni) {
            const int e = e0 + wn + ni * 8 + ((lane & 3) << 1);
            float* o = out + ((size_t)bh * S_ + t) * E_ + e;
            *(float2*)o            = make_float2(acc[mi][ni][0], acc[mi][ni][1]);
            *(float2*)(o + 8 * E_) = make_float2(acc[mi][ni][2], acc[mi][ni][3]);
        }
    }
    #undef ISSUE_CHUNK
}

// ---------------------------------------------------------------------------
extern "C" void kernel_launch(void* const* d_in, const int* in_sizes, int n_in,
                              void* d_out, int out_size) {
    (void)in_sizes; (void)n_in; (void)out_size;
    const float* src = (const float*)d_in[0];
    const float* tgt = (const float*)d_in[1];
    const float* enc = (const float*)d_in[2];
    const float* pa  = (const float*)d_in[3];
    const float* pb  = (const float*)d_in[4];
    const float* pg  = (const float*)d_in[5];
    float* out = (float*)d_out;

    cudaFuncSetAttribute(scores_mma,   cudaFuncAttributeMaxDynamicSharedMemorySize, SMEM_SC);
    cudaFuncSetAttribute(out_gemm_mma, cudaFuncAttributeMaxDynamicSharedMemorySize, SMEM_OG);

    scan_kernel<<<BH_, D_>>>(tgt, enc);
    prep_T<<<(B_ * S_ * E_) / 4 / 256, 256>>>(tgt);
    scores_mma<<<dim3(8, 8, BH_ * 2), 256, SMEM_SC>>>(src, tgt);
    softmax_kernel<<<dim3(32, BH_), 256>>>(pa, pb, pg);
    out_gemm_mma<<<dim3(8, 4, BH_), 256, SMEM_OG>>>(out);
}

// round 16
// speedup vs baseline: 3.6832x; 1.1376x over previous
#include <cuda_runtime.h>
#include <cuda_bf16.h>
#include <cstdint>

#define B_  4
#define S_  1024
#define E_  512
#define H_  8
#define D_  64
#define BH_ 32

// ---------------------------------------------------------------------------
// Scratch (__device__ globals; no runtime allocation allowed).
// ---------------------------------------------------------------------------
static __device__ float g_CC [(size_t)BH_ * S_ * D_];   //   8 MB [bh][t][d]
static __device__ float g_G  [(size_t)BH_ * S_ * S_];   // 128 MB [bh][s][t] grammar scores
static __device__ float g_Sem[(size_t)BH_ * S_ * S_];   // 128 MB [bh][s][t]
static __device__ __nv_bfloat16 g_Wh[(size_t)BH_ * S_ * S_];  // 64 MB [bh][s][t] W hi
static __device__ __nv_bfloat16 g_Wl[(size_t)BH_ * S_ * S_];  // 64 MB [bh][s][t] W lo
static __device__ __nv_bfloat16 g_Th[(size_t)B_ * S_ * E_];   //  4 MB [b][s][e] T hi
static __device__ __nv_bfloat16 g_Tl[(size_t)B_ * S_ * E_];   //  4 MB [b][s][e] T lo

__device__ __forceinline__ float hw_tanhf(float x) {
    float y;
    asm("tanh.approx.f32 %0, %1;" : "=f"(y) : "f"(x));
    return y;
}

__device__ __forceinline__ uint32_t smem_u32(const void* p) {
    uint32_t a;
    asm("{ .reg .u64 t; cvta.to.shared.u64 t, %1; cvt.u32.u64 %0, t; }" : "=r"(a) : "l"(p));
    return a;
}
__device__ __forceinline__ void ldsm_x4(uint32_t* r, uint32_t a) {
    asm volatile("ldmatrix.sync.aligned.m8n8.x4.shared.b16 {%0,%1,%2,%3}, [%4];"
        : "=r"(r[0]), "=r"(r[1]), "=r"(r[2]), "=r"(r[3]) : "r"(a));
}
__device__ __forceinline__ void ldsm_x2(uint32_t* r, uint32_t a) {
    asm volatile("ldmatrix.sync.aligned.m8n8.x2.shared.b16 {%0,%1}, [%2];"
        : "=r"(r[0]), "=r"(r[1]) : "r"(a));
}
__device__ __forceinline__ void ldsm_x4_t(uint32_t* r, uint32_t a) {
    asm volatile("ldmatrix.sync.aligned.m8n8.x4.trans.shared.b16 {%0,%1,%2,%3}, [%4];"
        : "=r"(r[0]), "=r"(r[1]), "=r"(r[2]), "=r"(r[3]) : "r"(a));
}
__device__ __forceinline__ void ldsm_x2_t(uint32_t* r, uint32_t a) {
    asm volatile("ldmatrix.sync.aligned.m8n8.x2.trans.shared.b16 {%0,%1}, [%2];"
        : "=r"(r[0]), "=r"(r[1]) : "r"(a));
}
__device__ __forceinline__ void mma16816(float* c, const uint32_t* a, const uint32_t* b) {
    asm volatile("mma.sync.aligned.m16n8k16.row.col.f32.bf16.bf16.f32 "
        "{%0,%1,%2,%3}, {%4,%5,%6,%7}, {%8,%9}, {%0,%1,%2,%3};"
        : "+f"(c[0]), "+f"(c[1]), "+f"(c[2]), "+f"(c[3])
        : "r"(a[0]), "r"(a[1]), "r"(a[2]), "r"(a[3]), "r"(b[0]), "r"(b[1]));
}
__device__ __forceinline__ uint32_t pack_bf16(__nv_bfloat16 a, __nv_bfloat16 b) {
    return ((uint32_t)__bfloat16_as_ushort(b) << 16) | __bfloat16_as_ushort(a);
}
__device__ __forceinline__ void cp_async16(uint32_t dst, const void* src) {
    asm volatile("cp.async.cg.shared.global [%0], [%1], 16;" :: "r"(dst), "l"(src));
}
#define CP_COMMIT() asm volatile("cp.async.commit_group;" ::: "memory")
#define CP_WAIT(n)  asm volatile("cp.async.wait_group %0;" :: "n"(n) : "memory")

// ---------------------------------------------------------------------------
// Kernel A: sequential scan (hardware tanh).
// ---------------------------------------------------------------------------
__global__ void scan_kernel(const float* __restrict__ tgt,
                            const float* __restrict__ enc) {
    const int bh = blockIdx.x, b = bh >> 3, h = bh & 7;
    const int d = threadIdx.x;
    const float pe = enc[h * D_ + d];
    const float* kp = tgt + (size_t)b * S_ * E_ + h * D_ + d;
    float* cp = g_CC + (size_t)bh * S_ * D_ + d;
    float carry = kp[0];
    for (int t = 0; t < S_; ++t) {
        float v = hw_tanhf(carry * pe);
        cp[(size_t)t * D_] = v;
        carry = kp[(size_t)t * E_] * v;
    }
}

// ---------------------------------------------------------------------------
// prep_T: target fp32 [b][s][e] -> hi/lo bf16, same layout.
// ---------------------------------------------------------------------------
__global__ __launch_bounds__(256) void prep_T(const float* __restrict__ tgt) {
    const size_t i4 = (size_t)blockIdx.x * 256 + threadIdx.x;
    const float4 v = ((const float4*)tgt)[i4];
    const __nv_bfloat16 h0 = __float2bfloat16(v.x);
    const __nv_bfloat16 h1 = __float2bfloat16(v.y);
    const __nv_bfloat16 h2 = __float2bfloat16(v.z);
    const __nv_bfloat16 h3 = __float2bfloat16(v.w);
    const __nv_bfloat16 l0 = __float2bfloat16(v.x - __bfloat162float(h0));
    const __nv_bfloat16 l1 = __float2bfloat16(v.y - __bfloat162float(h1));
    const __nv_bfloat16 l2 = __float2bfloat16(v.z - __bfloat162float(h2));
    const __nv_bfloat16 l3 = __float2bfloat16(v.w - __bfloat162float(h3));
    ((uint2*)g_Th)[i4] = make_uint2(pack_bf16(h0, h1), pack_bf16(h2, h3));
    ((uint2*)g_Tl)[i4] = make_uint2(pack_bf16(l0, l1), pack_bf16(l2, l3));
}

// ---------------------------------------------------------------------------
// Kernel B v4: score GEMM, ONE pass per CTA (grid.z = 2*BH), low-liveness.
// even z: Sem = (Q.K^T)/100 ; odd z: G = (Q.CC^T)/8.
// ---------------------------------------------------------------------------
#define SC_RST    72
#define SC_TILEB  (128 * SC_RST * 2)   // 18432 B
#define SC_QH     0
#define SC_QL     SC_TILEB
#define SC_PH     (2 * SC_TILEB)
#define SC_PL     (3 * SC_TILEB)
#define SMEM_SC   (4 * SC_TILEB)       // 73728 B

__device__ __forceinline__ void load_split_64(const float* __restrict__ g, int gstride,
                                              char* sh, char* sl, int tid) {
    #pragma unroll
    for (int i = 0; i < 8; ++i) {
        const int q = i * 256 + tid;
        const int row = q >> 4;
        const int col = (q & 15) << 2;
        const float4 v = *(const float4*)(g + (size_t)row * gstride + col);
        const __nv_bfloat16 h0 = __float2bfloat16(v.x);
        const __nv_bfloat16 h1 = __float2bfloat16(v.y);
        const __nv_bfloat16 h2 = __float2bfloat16(v.z);
        const __nv_bfloat16 h3 = __float2bfloat16(v.w);
        const __nv_bfloat16 l0 = __float2bfloat16(v.x - __bfloat162float(h0));
        const __nv_bfloat16 l1 = __float2bfloat16(v.y - __bfloat162float(h1));
        const __nv_bfloat16 l2 = __float2bfloat16(v.z - __bfloat162float(h2));
        const __nv_bfloat16 l3 = __float2bfloat16(v.w - __bfloat162float(h3));
        const uint32_t off = (uint32_t)(row * (SC_RST * 2) + col * 2);
        *(uint2*)(sh + off) = make_uint2(pack_bf16(h0, h1), pack_bf16(h2, h3));
        *(uint2*)(sl + off) = make_uint2(pack_bf16(l0, l1), pack_bf16(l2, l3));
    }
}

__global__ __launch_bounds__(256, 2) void scores_mma(const float* __restrict__ src,
                                                     const float* __restrict__ tgt) {
    extern __shared__ char smem[];
    const uint32_t sb = smem_u32(smem);

    const int tid = threadIdx.x, wid = tid >> 5, lane = tid & 31;
    const int zz = blockIdx.z;
    const int bh = zz >> 1, pass = zz & 1;
    const int b = bh >> 3, h = bh & 7;
    const int s0 = blockIdx.y << 7, t0 = blockIdx.x << 7;

    load_split_64(src + ((size_t)(b * S_ + s0)) * E_ + h * D_, E_,
                  smem + SC_QH, smem + SC_QL, tid);
    if (pass == 0)
        load_split_64(tgt + ((size_t)(b * S_ + t0)) * E_ + h * D_, E_,
                      smem + SC_PH, smem + SC_PL, tid);
    else
        load_split_64(g_CC + ((size_t)(bh * S_ + t0)) * D_, D_,
                      smem + SC_PH, smem + SC_PL, tid);
    __syncthreads();

    const int wm = (wid >> 2) * 64;
    const int wn = (wid & 3) * 32;
    const int a_r = lane & 15, a_c = (lane >> 4) << 3;
    const int b_r = lane & 7,  b_c = ((lane >> 3) & 1) << 3;

    float acc[4][4][4] = {};

    #pragma unroll
    for (int k = 0; k < 4; ++k) {
        const int k0 = k << 4;
        uint32_t Ah[4][4], Al[4][4];
        #pragma unroll
        for (int mi = 0; mi < 4; ++mi) {
            const uint32_t ro = (uint32_t)((wm + mi * 16 + a_r) * (SC_RST * 2) + (a_c + k0) * 2);
            ldsm_x4(Ah[mi], sb + SC_QH + ro);
            ldsm_x4(Al[mi], sb + SC_QL + ro);
        }
        #pragma unroll
        for (int ni = 0; ni < 4; ++ni) {
            uint32_t Bh[2], Bl[2];
            const uint32_t ro = (uint32_t)((wn + ni * 8 + b_r) * (SC_RST * 2) + (b_c + k0) * 2);
            ldsm_x2(Bh, sb + SC_PH + ro);
            ldsm_x2(Bl, sb + SC_PL + ro);
            #pragma unroll
            for (int mi = 0; mi < 4; ++mi) {
                mma16816(acc[mi][ni], Ah[mi], Bh);
                mma16816(acc[mi][ni], Al[mi], Bh);
                mma16816(acc[mi][ni], Ah[mi], Bl);
            }
        }
    }

    const float scale = pass ? 0.125f : 0.01f;
    float* dst = (pass ? g_G : g_Sem) + ((size_t)bh * S_) * S_;
    #pragma unroll
    for (int mi = 0; mi < 4; ++mi) {
        const int s = s0 + wm + mi * 16 + (lane >> 2);
        #pragma unroll
        for (int ni = 0; ni < 4; ++ni) {
            const int t = t0 + wn + ni * 8 + ((lane & 3) << 1);
            float* o = dst + (size_t)s * S_ + t;
            *(float2*)o            = make_float2(acc[mi][ni][0] * scale, acc[mi][ni][1] * scale);
            *(float2*)(o + 8 * S_) = make_float2(acc[mi][ni][2] * scale, acc[mi][ni][3] * scale);
        }
    }
}

// ---------------------------------------------------------------------------
// Kernel C: per-row double softmax; emits W as hi/lo bf16 [s][t] directly.
// ---------------------------------------------------------------------------
__global__ __launch_bounds__(256) void softmax_kernel(const float* __restrict__ pa,
                                                      const float* __restrict__ pb,
                                                      const float* __restrict__ pg) {
    const int bh = blockIdx.y;
    const int warp = threadIdx.x >> 5, lane = threadIdx.x & 31;
    const float alpha = *pa, beta = *pb, invg = 1.0f / *pg;

    for (int rr = 0; rr < 4; ++rr) {
        const int s = (blockIdx.x << 5) + (warp << 2) + rr;
        const size_t rbase = ((size_t)bh * S_ + s) * S_;
        const float* grow = g_G + rbase;
        const float* srow = g_Sem + rbase;

        float v[32];
        float m = -1e30f;
        #pragma unroll
        for (int g = 0; g < 8; ++g) {
            const float4 x = *(const float4*)(grow + g * 128 + lane * 4);
            v[g * 4]     = x.x; v[g * 4 + 1] = x.y;
            v[g * 4 + 2] = x.z; v[g * 4 + 3] = x.w;
            m = fmaxf(fmaxf(fmaxf(m, x.x), fmaxf(x.y, x.z)), x.w);
        }
        #pragma unroll
        for (int o = 16; o; o >>= 1) m = fmaxf(m, __shfl_xor_sync(0xffffffffu, m, o));

        float sum = 0.f;
        #pragma unroll
        for (int i = 0; i < 32; ++i) { v[i] = __expf(v[i] - m); sum += v[i]; }
        #pragma unroll
        for (int o = 16; o; o >>= 1) sum += __shfl_xor_sync(0xffffffffu, sum, o);
        const float inv = __fdividef(1.0f, sum);

        float m2 = -1e30f;
        #pragma unroll
        for (int g = 0; g < 8; ++g) {
            const float4 x = *(const float4*)(srow + g * 128 + lane * 4);
            const float xs[4] = {x.x, x.y, x.z, x.w};
            #pragma unroll
            for (int j = 0; j < 4; ++j) {
                float l = (alpha * xs[j] + beta * v[g * 4 + j] * inv) * invg;
                v[g * 4 + j] = l; m2 = fmaxf(m2, l);
            }
        }
        #pragma unroll
        for (int o = 16; o; o >>= 1) m2 = fmaxf(m2, __shfl_xor_sync(0xffffffffu, m2, o));

        float s2 = 0.f;
        #pragma unroll
        for (int i = 0; i < 32; ++i) { v[i] = __expf(v[i] - m2); s2 += v[i]; }
        #pragma unroll
        for (int o = 16; o; o >>= 1) s2 += __shfl_xor_sync(0xffffffffu, s2, o);
        const float inv2 = __fdividef(1.0f, s2);

        #pragma unroll
        for (int g = 0; g < 8; ++g) {
            float w[4];
            __nv_bfloat16 h[4], l[4];
            #pragma unroll
            for (int j = 0; j < 4; ++j) {
                w[j] = v[g * 4 + j] * inv2;
                h[j] = __float2bfloat16(w[j]);
                l[j] = __float2bfloat16(w[j] - __bfloat162float(h[j]));
            }
            const size_t off = rbase + g * 128 + lane * 4;
            *(uint2*)(g_Wh + off) = make_uint2(pack_bf16(h[0], h[1]), pack_bf16(h[2], h[3]));
            *(uint2*)(g_Wl + off) = make_uint2(pack_bf16(l[0], l[1]), pack_bf16(l[2], l[3]));
        }
    }
}

// ---------------------------------------------------------------------------
// Kernel D v8: split-bf16 HMMA output GEMM, 3-stage cp.async pipeline,
// ONE __syncthreads per chunk, 2 CTAs/SM, low-liveness fragment schedule.
// ---------------------------------------------------------------------------
#define KC_       32
#define NCHUNK_   (S_ / KC_)           // 32
#define NSTAGE_   3
#define ORST_     136                  // bf16 per smem row
#define OROWB_    (ORST_ * 2)          // 272 B
#define OTILEB_   (KC_ * OROWB_)       // 8704 B
#define OFF_WH_   0
#define OFF_WL_   OTILEB_
#define OFF_TH_   (2 * OTILEB_)
#define OFF_TL_   (3 * OTILEB_)
#define OBUFB_    (4 * OTILEB_)        // 34816 B
#define SMEM_OG   (NSTAGE_ * OBUFB_)   // 104448 B

__global__ __launch_bounds__(256, 2) void out_gemm_mma(float* __restrict__ out) {
    extern __shared__ char smem[];
    const uint32_t sb = smem_u32(smem);

    const int tid = threadIdx.x, wid = tid >> 5, lane = tid & 31;
    const int bh = blockIdx.z, b = bh >> 3;
    const int t0 = blockIdx.x << 7, e0 = blockIdx.y << 7;

    const __nv_bfloat16* WHp = g_Wh + (size_t)bh * S_ * S_ + t0;   // + s*S_
    const __nv_bfloat16* WLp = g_Wl + (size_t)bh * S_ * S_ + t0;
    const __nv_bfloat16* THp = g_Th + (size_t)b * S_ * E_ + e0;    // + s*E_
    const __nv_bfloat16* TLp = g_Tl + (size_t)b * S_ * E_ + e0;

    const int wm = (wid >> 2) * 64;       // t offset 0/64
    const int wn = (wid & 3) * 32;        // e offset 0..96

    const int q0r = (tid * 2) >> 4,       q0c = ((tid * 2) & 15) << 3;
    const int q1r = (tid * 2 + 1) >> 4,   q1c = ((tid * 2 + 1) & 15) << 3;

    #define ISSUE_CHUNK(sc, buf) do {                                              \
        const uint32_t db = sb + (uint32_t)(buf) * OBUFB_;                         \
        const uint32_t o0 = (uint32_t)(q0r * OROWB_ + q0c * 2);                    \
        const uint32_t o1 = (uint32_t)(q1r * OROWB_ + q1c * 2);                    \
        const size_t gw0 = (size_t)((sc) + q0r) * S_ + q0c;                        \
        const size_t gw1 = (size_t)((sc) + q1r) * S_ + q1c;                        \
        const size_t gt0 = (size_t)((sc) + q0r) * E_ + q0c;                        \
        const size_t gt1 = (size_t)((sc) + q1r) * E_ + q1c;                        \
        cp_async16(db + OFF_WH_ + o0, WHp + gw0);                                  \
        cp_async16(db + OFF_WH_ + o1, WHp + gw1);                                  \
        cp_async16(db + OFF_WL_ + o0, WLp + gw0);                                  \
        cp_async16(db + OFF_WL_ + o1, WLp + gw1);                                  \
        cp_async16(db + OFF_TH_ + o0, THp + gt0);                                  \
        cp_async16(db + OFF_TH_ + o1, THp + gt1);                                  \
        cp_async16(db + OFF_TL_ + o0, TLp + gt0);                                  \
        cp_async16(db + OFF_TL_ + o1, TLp + gt1);                                  \
        CP_COMMIT();                                                               \
    } while (0)

    float acc[4][4][4] = {};

    ISSUE_CHUNK(0, 0);
    ISSUE_CHUNK(KC_, 1);

    const int a_s = (lane & 7) + ((lane >> 4) << 3);
    const int a_t = ((lane >> 3) & 1) << 3;
    const int b_s = (lane & 7) + (((lane >> 3) & 1) << 3);

    int buf = 0;
    for (int c = 0; c < NCHUNK_; ++c) {
        if (c == NCHUNK_ - 1) { CP_WAIT(0); } else { CP_WAIT(1); }
        __syncthreads();

        if (c + 2 < NCHUNK_) {
            int nb = buf + 2; if (nb >= NSTAGE_) nb -= NSTAGE_;
            ISSUE_CHUNK((c + 2) * KC_, nb);
        }

        const uint32_t base = sb + (uint32_t)buf * OBUFB_;
        #pragma unroll
        for (int kk = 0; kk < 2; ++kk) {
            const int k0 = kk << 4;
            uint32_t Ah[4][4], Al[4][4];
            #pragma unroll
            for (int mi = 0; mi < 4; ++mi) {
                const uint32_t ro = (uint32_t)((k0 + a_s) * OROWB_ + (wm + mi * 16 + a_t) * 2);
                ldsm_x4_t(Ah[mi], base + OFF_WH_ + ro);
                ldsm_x4_t(Al[mi], base + OFF_WL_ + ro);
            }
            #pragma unroll
            for (int ni = 0; ni < 4; ++ni) {
                uint32_t Bh[2], Bl[2];
                const uint32_t ro = (uint32_t)((k0 + b_s) * OROWB_ + (wn + ni * 8) * 2);
                ldsm_x2_t(Bh, base + OFF_TH_ + ro);
                ldsm_x2_t(Bl, base + OFF_TL_ + ro);
                #pragma unroll
                for (int mi = 0; mi < 4; ++mi) {
                    mma16816(acc[mi][ni], Ah[mi], Bh);
                    mma16816(acc[mi][ni], Al[mi], Bh);
                    mma16816(acc[mi][ni], Ah[mi], Bl);
                }
            }
        }

        if (++buf == NSTAGE_) buf = 0;
    }

    #pragma unroll
    for (int mi = 0; mi < 4; ++mi) {
        const int t = t0 + wm + mi * 16 + (lane >> 2);
        #pragma unroll
        for (int ni = 0; ni < 4; ++ni) {
            const int e = e0 + wn + ni * 8 + ((lane & 3) << 1);
            float* o = out + ((size_t)bh * S_ + t) * E_ + e;
            *(float2*)o            = make_float2(acc[mi][ni][0], acc[mi][ni][1]);
            *(float2*)(o + 8 * E_) = make_float2(acc[mi][ni][2], acc[mi][ni][3]);
        }
    }
    #undef ISSUE_CHUNK
}

// ---------------------------------------------------------------------------
extern "C" void kernel_launch(void* const* d_in, const int* in_sizes, int n_in,
                              void* d_out, int out_size) {
    (void)in_sizes; (void)n_in; (void)out_size;
    const float* src = (const float*)d_in[0];
    const float* tgt = (const float*)d_in[1];
    const float* enc = (const float*)d_in[2];
    const float* pa  = (const float*)d_in[3];
    const float* pb  = (const float*)d_in[4];
    const float* pg  = (const float*)d_in[5];
    float* out = (float*)d_out;

    cudaFuncSetAttribute(scores_mma,   cudaFuncAttributeMaxDynamicSharedMemorySize, SMEM_SC);
    cudaFuncSetAttribute(out_gemm_mma, cudaFuncAttributeMaxDynamicSharedMemorySize, SMEM_OG);

    scan_kernel<<<BH_, D_>>>(tgt, enc);
    prep_T<<<(B_ * S_ * E_) / 4 / 256, 256>>>(tgt);
    scores_mma<<<dim3(8, 8, BH_ * 2), 256, SMEM_SC>>>(src, tgt);
    softmax_kernel<<<dim3(32, BH_), 256>>>(pa, pb, pg);
    out_gemm_mma<<<dim3(8, 4, BH_), 256, SMEM_OG>>>(out);
}